// round 3
// baseline (speedup 1.0000x reference)
#include <cuda_runtime.h>
#include <cuda_bf16.h>
#include <cstdint>

// Problem constants: qkv (B,S,3,H,D) fp32
#define B_   2
#define S_   2048
#define H_   16
#define D_   64
#define QKV_LD 3072
#define BH_  32

// smem panels: rows of 64 bf16 = 128B, SW128 swizzled
#define SM_A_HI 0
#define SM_A_LO 16384
#define SM_B_HI 32768
#define SM_B_LO 40960
#define SM_TOTAL 49152

// Scratch: intermediates as bf16 hi/lo split pairs (same total bytes as fp32)
__device__ __nv_bfloat16 g_a_hi[(size_t)BH_ * S_ * S_];   // 268 MB
__device__ __nv_bfloat16 g_a_lo[(size_t)BH_ * S_ * S_];   // 268 MB
__device__ __nv_bfloat16 g_o2_hi[(size_t)BH_ * S_ * D_];  // 8 MB
__device__ __nv_bfloat16 g_o2_lo[(size_t)BH_ * S_ * D_];  // 8 MB

__device__ __forceinline__ uint32_t smem_u32(const void* p) {
    uint32_t a;
    asm("{ .reg .u64 t; cvta.to.shared.u64 t, %1; cvt.u32.u64 %0, t; }" : "=r"(a) : "l"(p));
    return a;
}
__device__ __forceinline__ uint32_t sw128(uint32_t off) { return off ^ ((off >> 3) & 0x70); }

__device__ __forceinline__ void split_pack(float x0, float x1, uint32_t& hp, uint32_t& lp) {
    __nv_bfloat16 h0 = __float2bfloat16(x0);
    __nv_bfloat16 l0 = __float2bfloat16(x0 - __bfloat162float(h0));
    __nv_bfloat16 h1 = __float2bfloat16(x1);
    __nv_bfloat16 l1 = __float2bfloat16(x1 - __bfloat162float(h1));
    hp = (uint32_t)__bfloat16_as_ushort(h0) | ((uint32_t)__bfloat16_as_ushort(h1) << 16);
    lp = (uint32_t)__bfloat16_as_ushort(l0) | ((uint32_t)__bfloat16_as_ushort(l1) << 16);
}

// ---------------------------------------------------------------------------
// ldmatrix wrappers. Address: row = r_base + (lane&15), col = c_base + (lane>>4)*8
// (elements; 2B each; rows are 128B, SW128-swizzled)
// ---------------------------------------------------------------------------
__device__ __forceinline__ void ldsm_x4(uint32_t base, int r_base, int c_base, int lane, uint32_t r[4]) {
    uint32_t off = (uint32_t)((r_base + (lane & 15)) * 128 + (c_base + ((lane >> 4) << 3)) * 2);
    uint32_t addr = base + sw128(off);
    asm volatile("ldmatrix.sync.aligned.m8n8.x4.shared.b16 {%0,%1,%2,%3}, [%4];"
                 : "=r"(r[0]), "=r"(r[1]), "=r"(r[2]), "=r"(r[3]) : "r"(addr));
}
__device__ __forceinline__ void ldsm_x4_t(uint32_t base, int r_base, int c_base, int lane, uint32_t r[4]) {
    uint32_t off = (uint32_t)((r_base + (lane & 15)) * 128 + (c_base + ((lane >> 4) << 3)) * 2);
    uint32_t addr = base + sw128(off);
    asm volatile("ldmatrix.sync.aligned.m8n8.x4.trans.shared.b16 {%0,%1,%2,%3}, [%4];"
                 : "=r"(r[0]), "=r"(r[1]), "=r"(r[2]), "=r"(r[3]) : "r"(addr));
}

__device__ __forceinline__ void mma16816(float c[4], const uint32_t a[4], const uint32_t b[2]) {
    asm volatile("mma.sync.aligned.m16n8k16.row.col.f32.bf16.bf16.f32 "
                 "{%0,%1,%2,%3}, {%4,%5,%6,%7}, {%8,%9}, {%0,%1,%2,%3};"
                 : "+f"(c[0]), "+f"(c[1]), "+f"(c[2]), "+f"(c[3])
                 : "r"(a[0]), "r"(a[1]), "r"(a[2]), "r"(a[3]), "r"(b[0]), "r"(b[1]));
}

// ---------------------------------------------------------------------------
// One K=64 chunk of the split GEMM: acc += Ah*Bh + Ah*Bl + Al*Bh
// Warp tile 32(m) x 32(n). BT=true: B panel stored [k][n]; else [n][k].
// ---------------------------------------------------------------------------
template <bool BT>
__device__ __forceinline__ void mma_chunk(uint32_t aHi, uint32_t aLo, uint32_t bHi, uint32_t bLo,
                                          int warp_m, int warp_n, int lane, float acc[2][4][4]) {
#pragma unroll
    for (int ks = 0; ks < 4; ks++) {
        int kk = ks * 16;
        uint32_t ah[2][4], al[2][4];
#pragma unroll
        for (int mf = 0; mf < 2; mf++) {
            ldsm_x4(aHi, warp_m + mf * 16, kk, lane, ah[mf]);
            ldsm_x4(aLo, warp_m + mf * 16, kk, lane, al[mf]);
        }
        uint32_t bh[4][2], bl[4][2];
#pragma unroll
        for (int nq = 0; nq < 2; nq++) {
            uint32_t r[4], s[4];
            if (BT) {
                ldsm_x4_t(bHi, kk, warp_n + nq * 16, lane, r);
                ldsm_x4_t(bLo, kk, warp_n + nq * 16, lane, s);
                bh[2*nq][0] = r[0]; bh[2*nq][1] = r[1]; bh[2*nq+1][0] = r[2]; bh[2*nq+1][1] = r[3];
                bl[2*nq][0] = s[0]; bl[2*nq][1] = s[1]; bl[2*nq+1][0] = s[2]; bl[2*nq+1][1] = s[3];
            } else {
                ldsm_x4(bHi, warp_n + nq * 16, kk, lane, r);
                ldsm_x4(bLo, warp_n + nq * 16, kk, lane, s);
                bh[2*nq][0] = r[0]; bh[2*nq][1] = r[2]; bh[2*nq+1][0] = r[1]; bh[2*nq+1][1] = r[3];
                bl[2*nq][0] = s[0]; bl[2*nq][1] = s[2]; bl[2*nq+1][0] = s[1]; bl[2*nq+1][1] = s[3];
            }
        }
#pragma unroll
        for (int mf = 0; mf < 2; mf++)
#pragma unroll
            for (int nf = 0; nf < 4; nf++) {
                mma16816(acc[mf][nf], ah[mf], bh[nf]);
                mma16816(acc[mf][nf], ah[mf], bl[nf]);
                mma16816(acc[mf][nf], al[mf], bh[nf]);
            }
    }
}

// ---------------------------------------------------------------------------
// Loaders (256 threads)
// ---------------------------------------------------------------------------
__device__ __forceinline__ void load_split_f32(const float* __restrict__ g, int ld,
                                               char* smHi, char* smLo, int rows, int tid) {
    for (int idx = tid; idx < rows * 32; idx += 256) {
        int r = idx >> 5, c2 = idx & 31;
        float2 v = *reinterpret_cast<const float2*>(g + (size_t)r * ld + c2 * 2);
        uint32_t hp, lp;
        split_pack(v.x, v.y, hp, lp);
        uint32_t off = sw128((uint32_t)(r * 128 + c2 * 4));
        *reinterpret_cast<uint32_t*>(smHi + off) = hp;
        *reinterpret_cast<uint32_t*>(smLo + off) = lp;
    }
}
__device__ __forceinline__ void load_bf16_pair(const uint32_t* __restrict__ gH,
                                               const uint32_t* __restrict__ gL, int ld_u32,
                                               char* smHi, char* smLo, int rows, int tid) {
    for (int idx = tid; idx < rows * 32; idx += 256) {
        int r = idx >> 5, c2 = idx & 31;
        uint32_t off = sw128((uint32_t)(r * 128 + c2 * 4));
        *reinterpret_cast<uint32_t*>(smHi + off) = gH[(size_t)r * ld_u32 + c2];
        *reinterpret_cast<uint32_t*>(smLo + off) = gL[(size_t)r * ld_u32 + c2];
    }
}

// ===========================================================================
// K1: a1 = tril(q k^T). CTA: 128(t) x 64(s). B = k[s][d] -> n-major (non-trans).
// ===========================================================================
__global__ __launch_bounds__(256, 2) void k1_qk(const float* __restrict__ qkv) {
    int st = blockIdx.x, tt = blockIdx.y, bh = blockIdx.z;
    if (st > 2 * tt + 1) return;
    __shared__ __align__(1024) char smem[SM_TOTAL];
    int tid = threadIdx.x, lane = tid & 31, wid = tid >> 5;
    int warp_m = (wid >> 1) * 32, warp_n = (wid & 1) * 32;
    int b = bh >> 4, h = bh & 15;

    const float* qb = qkv + (size_t)(b * S_ + tt * 128) * QKV_LD + h * D_;
    const float* kb = qkv + (size_t)(b * S_ + st * 64) * QKV_LD + (H_ + h) * D_;
    load_split_f32(qb, QKV_LD, smem + SM_A_HI, smem + SM_A_LO, 128, tid);
    load_split_f32(kb, QKV_LD, smem + SM_B_HI, smem + SM_B_LO, 64, tid);
    __syncthreads();

    uint32_t sb = smem_u32(smem);
    float acc[2][4][4] = {};
    mma_chunk<false>(sb + SM_A_HI, sb + SM_A_LO, sb + SM_B_HI, sb + SM_B_LO, warp_m, warp_n, lane, acc);

    int r0 = lane >> 2, cp = (lane & 3) * 2;
#pragma unroll
    for (int mf = 0; mf < 2; mf++)
#pragma unroll
        for (int half = 0; half < 2; half++) {
            int t = tt * 128 + warp_m + mf * 16 + half * 8 + r0;
            __nv_bfloat16* ah = g_a_hi + ((size_t)bh * S_ + t) * S_ + st * 64;
            __nv_bfloat16* al = g_a_lo + ((size_t)bh * S_ + t) * S_ + st * 64;
#pragma unroll
            for (int nf = 0; nf < 4; nf++) {
                int c = warp_n + nf * 8 + cp;
                int s = st * 64 + c;
                float x0 = (s     <= t) ? acc[mf][nf][half * 2 + 0] : 0.0f;
                float x1 = (s + 1 <= t) ? acc[mf][nf][half * 2 + 1] : 0.0f;
                uint32_t hp, lp;
                split_pack(x0, x1, hp, lp);
                *reinterpret_cast<uint32_t*>(ah + c) = hp;
                *reinterpret_cast<uint32_t*>(al + c) = lp;
            }
        }
}

// ===========================================================================
// K2: o2 = a1 k. CTA: 128(t) x 64(d), K = s chunks of 64. B trans ([s][d] k-major).
// ===========================================================================
__global__ __launch_bounds__(256, 2) void k2_o2(const float* __restrict__ qkv) {
    int tt = blockIdx.x, bh = blockIdx.y;
    __shared__ __align__(1024) char smem[SM_TOTAL];
    int tid = threadIdx.x, lane = tid & 31, wid = tid >> 5;
    int warp_m = (wid >> 1) * 32, warp_n = (wid & 1) * 32;
    int b = bh >> 4, h = bh & 15;
    uint32_t sb = smem_u32(smem);

    const uint32_t* aH = reinterpret_cast<const uint32_t*>(g_a_hi + ((size_t)bh * S_ + tt * 128) * S_);
    const uint32_t* aL = reinterpret_cast<const uint32_t*>(g_a_lo + ((size_t)bh * S_ + tt * 128) * S_);
    float acc[2][4][4] = {};
    int nch = 2 * tt + 2;
    for (int ch = 0; ch < nch; ch++) {
        load_bf16_pair(aH + ch * 32, aL + ch * 32, S_ / 2, smem + SM_A_HI, smem + SM_A_LO, 128, tid);
        const float* kc = qkv + (size_t)(b * S_ + ch * 64) * QKV_LD + (H_ + h) * D_;
        load_split_f32(kc, QKV_LD, smem + SM_B_HI, smem + SM_B_LO, 64, tid);
        __syncthreads();
        mma_chunk<true>(sb + SM_A_HI, sb + SM_A_LO, sb + SM_B_HI, sb + SM_B_LO, warp_m, warp_n, lane, acc);
        __syncthreads();
    }

    int r0 = lane >> 2, cp = (lane & 3) * 2;
#pragma unroll
    for (int mf = 0; mf < 2; mf++)
#pragma unroll
        for (int half = 0; half < 2; half++) {
            int t = tt * 128 + warp_m + mf * 16 + half * 8 + r0;
            __nv_bfloat16* oh = g_o2_hi + ((size_t)bh * S_ + t) * D_;
            __nv_bfloat16* ol = g_o2_lo + ((size_t)bh * S_ + t) * D_;
#pragma unroll
            for (int nf = 0; nf < 4; nf++) {
                int d = warp_n + nf * 8 + cp;
                uint32_t hp, lp;
                split_pack(acc[mf][nf][half * 2 + 0], acc[mf][nf][half * 2 + 1], hp, lp);
                *reinterpret_cast<uint32_t*>(oh + d) = hp;
                *reinterpret_cast<uint32_t*>(ol + d) = lp;
            }
        }
}

// ===========================================================================
// K3: a = 2*a1 - tril(o2 k^T). CTA 128(t) x 64(s). In-place RMW on g_a.
// ===========================================================================
__global__ __launch_bounds__(256, 2) void k3_a2(const float* __restrict__ qkv) {
    int st = blockIdx.x, tt = blockIdx.y, bh = blockIdx.z;
    if (st > 2 * tt + 1) return;
    __shared__ __align__(1024) char smem[SM_TOTAL];
    int tid = threadIdx.x, lane = tid & 31, wid = tid >> 5;
    int warp_m = (wid >> 1) * 32, warp_n = (wid & 1) * 32;
    int b = bh >> 4, h = bh & 15;

    const uint32_t* oH = reinterpret_cast<const uint32_t*>(g_o2_hi + ((size_t)bh * S_ + tt * 128) * D_);
    const uint32_t* oL = reinterpret_cast<const uint32_t*>(g_o2_lo + ((size_t)bh * S_ + tt * 128) * D_);
    load_bf16_pair(oH, oL, D_ / 2, smem + SM_A_HI, smem + SM_A_LO, 128, tid);
    const float* kb = qkv + (size_t)(b * S_ + st * 64) * QKV_LD + (H_ + h) * D_;
    load_split_f32(kb, QKV_LD, smem + SM_B_HI, smem + SM_B_LO, 64, tid);
    __syncthreads();

    uint32_t sb = smem_u32(smem);
    float acc[2][4][4] = {};
    mma_chunk<false>(sb + SM_A_HI, sb + SM_A_LO, sb + SM_B_HI, sb + SM_B_LO, warp_m, warp_n, lane, acc);

    int r0 = lane >> 2, cp = (lane & 3) * 2;
#pragma unroll
    for (int mf = 0; mf < 2; mf++)
#pragma unroll
        for (int half = 0; half < 2; half++) {
            int t = tt * 128 + warp_m + mf * 16 + half * 8 + r0;
            __nv_bfloat16* ah = g_a_hi + ((size_t)bh * S_ + t) * S_ + st * 64;
            __nv_bfloat16* al = g_a_lo + ((size_t)bh * S_ + t) * S_ + st * 64;
#pragma unroll
            for (int nf = 0; nf < 4; nf++) {
                int c = warp_n + nf * 8 + cp;
                int s = st * 64 + c;
                uint32_t hv = *reinterpret_cast<const uint32_t*>(ah + c);
                uint32_t lv = *reinterpret_cast<const uint32_t*>(al + c);
                float a10 = __bfloat162float(__ushort_as_bfloat16((unsigned short)(hv & 0xFFFF)))
                          + __bfloat162float(__ushort_as_bfloat16((unsigned short)(lv & 0xFFFF)));
                float a11 = __bfloat162float(__ushort_as_bfloat16((unsigned short)(hv >> 16)))
                          + __bfloat162float(__ushort_as_bfloat16((unsigned short)(lv >> 16)));
                float x0 = (s     <= t) ? 2.0f * a10 - acc[mf][nf][half * 2 + 0] : 0.0f;
                float x1 = (s + 1 <= t) ? 2.0f * a11 - acc[mf][nf][half * 2 + 1] : 0.0f;
                uint32_t hp, lp;
                split_pack(x0, x1, hp, lp);
                *reinterpret_cast<uint32_t*>(ah + c) = hp;
                *reinterpret_cast<uint32_t*>(al + c) = lp;
            }
        }
}

// ===========================================================================
// K4: out = a v. CTA 128(t) x 64(d), K = s chunks. fp32 out (B,S,H,D).
// ===========================================================================
__global__ __launch_bounds__(256, 2) void k4_out(const float* __restrict__ qkv,
                                                 float* __restrict__ out) {
    int tt = blockIdx.x, bh = blockIdx.y;
    __shared__ __align__(1024) char smem[SM_TOTAL];
    int tid = threadIdx.x, lane = tid & 31, wid = tid >> 5;
    int warp_m = (wid >> 1) * 32, warp_n = (wid & 1) * 32;
    int b = bh >> 4, h = bh & 15;
    uint32_t sb = smem_u32(smem);

    const uint32_t* aH = reinterpret_cast<const uint32_t*>(g_a_hi + ((size_t)bh * S_ + tt * 128) * S_);
    const uint32_t* aL = reinterpret_cast<const uint32_t*>(g_a_lo + ((size_t)bh * S_ + tt * 128) * S_);
    float acc[2][4][4] = {};
    int nch = 2 * tt + 2;
    for (int ch = 0; ch < nch; ch++) {
        load_bf16_pair(aH + ch * 32, aL + ch * 32, S_ / 2, smem + SM_A_HI, smem + SM_A_LO, 128, tid);
        const float* vc = qkv + (size_t)(b * S_ + ch * 64) * QKV_LD + (2 * H_ + h) * D_;
        load_split_f32(vc, QKV_LD, smem + SM_B_HI, smem + SM_B_LO, 64, tid);
        __syncthreads();
        mma_chunk<true>(sb + SM_A_HI, sb + SM_A_LO, sb + SM_B_HI, sb + SM_B_LO, warp_m, warp_n, lane, acc);
        __syncthreads();
    }

    int r0 = lane >> 2, cp = (lane & 3) * 2;
#pragma unroll
    for (int mf = 0; mf < 2; mf++)
#pragma unroll
        for (int half = 0; half < 2; half++) {
            int t = tt * 128 + warp_m + mf * 16 + half * 8 + r0;
            float* op = out + ((size_t)(b * S_ + t)) * (H_ * D_) + h * D_;
#pragma unroll
            for (int nf = 0; nf < 4; nf++) {
                int d = warp_n + nf * 8 + cp;
                float2 v = make_float2(acc[mf][nf][half * 2 + 0], acc[mf][nf][half * 2 + 1]);
                *reinterpret_cast<float2*>(op + d) = v;
            }
        }
}

// ===========================================================================
extern "C" void kernel_launch(void* const* d_in, const int* in_sizes, int n_in,
                              void* d_out, int out_size) {
    const float* qkv = (const float*)d_in[0];
    float* out = (float*)d_out;

    dim3 blk(256);
    dim3 grid_tri(32, 16, BH_);   // (st 64-wide, tt 128-wide, bh); st > 2tt+1 exits
    dim3 grid_row(16, BH_);       // (tt, bh)

    k1_qk <<<grid_tri, blk>>>(qkv);
    k2_o2 <<<grid_row, blk>>>(qkv);
    k3_a2 <<<grid_tri, blk>>>(qkv);
    k4_out<<<grid_row, blk>>>(qkv, out);
}

// round 4
// speedup vs baseline: 8.7667x; 8.7667x over previous
#include <cuda_runtime.h>
#include <cuda_bf16.h>
#include <cstdint>

// Problem constants: qkv (B,S,3,H,D) fp32
#define B_   2
#define S_   2048
#define H_   16
#define D_   64
#define BH_  32

// ---------------------------------------------------------------------------
// Pre-split scratch: bf16 hi/lo, layout [bh][s][64] (rows of 128B)
// q is pre-scaled by 2.0 (folds the "2*a1" into one accumulator in pass B).
// o2 is stored NEGATED (so pass B just accumulates: acc = 2*s1 + (-s2)).
// ---------------------------------------------------------------------------
__device__ uint32_t g_q2h[(size_t)BH_ * S_ * 32];  // 8MB each (u32 = 2 bf16)
__device__ uint32_t g_q2l[(size_t)BH_ * S_ * 32];
__device__ uint32_t g_kh [(size_t)BH_ * S_ * 32];
__device__ uint32_t g_kl [(size_t)BH_ * S_ * 32];
__device__ uint32_t g_vh [(size_t)BH_ * S_ * 32];
__device__ uint32_t g_vl [(size_t)BH_ * S_ * 32];
__device__ uint32_t g_o2h[(size_t)BH_ * S_ * 32];
__device__ uint32_t g_o2l[(size_t)BH_ * S_ * 32];

__device__ __forceinline__ uint32_t smem_u32(const void* p) {
    uint32_t a;
    asm("{ .reg .u64 t; cvta.to.shared.u64 t, %1; cvt.u32.u64 %0, t; }" : "=r"(a) : "l"(p));
    return a;
}
__device__ __forceinline__ uint32_t sw128(uint32_t off) { return off ^ ((off >> 3) & 0x70); }

// split pair (x0,x1) -> bf16x2 hi packed + bf16x2 lo packed (round-to-nearest)
__device__ __forceinline__ void split_pair(float x0, float x1, uint32_t& hp, uint32_t& lp) {
    asm("cvt.rn.bf16x2.f32 %0, %1, %2;" : "=r"(hp) : "f"(x1), "f"(x0));
    float l0 = x0 - __uint_as_float(hp << 16);
    float l1 = x1 - __uint_as_float(hp & 0xFFFF0000u);
    asm("cvt.rn.bf16x2.f32 %0, %1, %2;" : "=r"(lp) : "f"(l1), "f"(l0));
}

// ---------------------------------------------------------------------------
// ldmatrix / mma (fragment mappings validated in round 3)
// ---------------------------------------------------------------------------
__device__ __forceinline__ void ldsm_x4(uint32_t base, int r_base, int c_base, int lane, uint32_t r[4]) {
    uint32_t off = (uint32_t)((r_base + (lane & 15)) * 128 + (c_base + ((lane >> 4) << 3)) * 2);
    uint32_t addr = base + sw128(off);
    asm volatile("ldmatrix.sync.aligned.m8n8.x4.shared.b16 {%0,%1,%2,%3}, [%4];"
                 : "=r"(r[0]), "=r"(r[1]), "=r"(r[2]), "=r"(r[3]) : "r"(addr));
}
__device__ __forceinline__ void ldsm_x4_t(uint32_t base, int r_base, int c_base, int lane, uint32_t r[4]) {
    uint32_t off = (uint32_t)((r_base + (lane & 15)) * 128 + (c_base + ((lane >> 4) << 3)) * 2);
    uint32_t addr = base + sw128(off);
    asm volatile("ldmatrix.sync.aligned.m8n8.x4.trans.shared.b16 {%0,%1,%2,%3}, [%4];"
                 : "=r"(r[0]), "=r"(r[1]), "=r"(r[2]), "=r"(r[3]) : "r"(addr));
}
__device__ __forceinline__ void mma16816(float c[4], const uint32_t a[4], const uint32_t b[2]) {
    asm volatile("mma.sync.aligned.m16n8k16.row.col.f32.bf16.bf16.f32 "
                 "{%0,%1,%2,%3}, {%4,%5,%6,%7}, {%8,%9}, {%0,%1,%2,%3};"
                 : "+f"(c[0]), "+f"(c[1]), "+f"(c[2]), "+f"(c[3])
                 : "r"(a[0]), "r"(a[1]), "r"(a[2]), "r"(a[3]), "r"(b[0]), "r"(b[1]));
}

// acc (m16 x n64, 8 frags) -> A-operand frags (m16 x k64, 4 kfrags), hi/lo split
__device__ __forceinline__ void acc_to_afrag(const float acc[8][4], uint32_t ah[4][4], uint32_t al[4][4]) {
#pragma unroll
    for (int kf = 0; kf < 4; kf++) {
        split_pair(acc[2*kf  ][0], acc[2*kf  ][1], ah[kf][0], al[kf][0]);
        split_pair(acc[2*kf  ][2], acc[2*kf  ][3], ah[kf][1], al[kf][1]);
        split_pair(acc[2*kf+1][0], acc[2*kf+1][1], ah[kf][2], al[kf][2]);
        split_pair(acc[2*kf+1][2], acc[2*kf+1][3], ah[kf][3], al[kf][3]);
    }
}

// ---------------------------------------------------------------------------
// cp.async chunk loader: 64 rows x 128B (hi + lo panels), SW128 swizzled
// ---------------------------------------------------------------------------
__device__ __forceinline__ void cpa16(uint32_t smaddr, const void* gaddr) {
    asm volatile("cp.async.cg.shared.global [%0], [%1], 16;" :: "r"(smaddr), "l"(gaddr));
}
__device__ __forceinline__ void issue_panel(const uint32_t* gH, const uint32_t* gL,
                                            uint32_t smH, uint32_t smL, int tid) {
    for (int i = tid; i < 512; i += 256) {
        int r = i >> 3, c = i & 7;
        uint32_t off = sw128((uint32_t)(r * 128 + c * 16));
        cpa16(smH + off, gH + r * 32 + c * 4);
        cpa16(smL + off, gL + r * 32 + c * 4);
    }
}
#define CP_COMMIT() asm volatile("cp.async.commit_group;" ::: "memory")
#define CP_WAIT1()  asm volatile("cp.async.wait_group 1;" ::: "memory")
#define CP_WAIT0()  asm volatile("cp.async.wait_group 0;" ::: "memory")

// stage a [rows][64]bf16 split pair from gmem (contiguous rows) into SW128 panels
__device__ __forceinline__ void stage_panel(const uint32_t* gH, const uint32_t* gL,
                                            char* smH, char* smL, int rows, int tid) {
    for (int idx = tid; idx < rows * 32; idx += 256) {
        int r = idx >> 5, c = idx & 31;
        uint32_t off = sw128((uint32_t)(r * 128 + c * 4));
        *reinterpret_cast<uint32_t*>(smH + off) = gH[r * 32 + c];
        *reinterpret_cast<uint32_t*>(smL + off) = gL[r * 32 + c];
    }
}

// B-frags from k-chunk, non-trans ([n][k] panel), n=64 -> 8 frags
__device__ __forceinline__ void load_b_nt(uint32_t baseH, uint32_t baseL, int kk, int lane,
                                          uint32_t bh[8][2], uint32_t bl[8][2]) {
#pragma unroll
    for (int nq = 0; nq < 4; nq++) {
        uint32_t r[4], s[4];
        ldsm_x4(baseH, nq * 16, kk, lane, r);
        ldsm_x4(baseL, nq * 16, kk, lane, s);
        bh[2*nq][0] = r[0]; bh[2*nq][1] = r[2]; bh[2*nq+1][0] = r[1]; bh[2*nq+1][1] = r[3];
        bl[2*nq][0] = s[0]; bl[2*nq][1] = s[2]; bl[2*nq+1][0] = s[1]; bl[2*nq+1][1] = s[3];
    }
}
// B-frags trans ([k][n] panel), n=64
__device__ __forceinline__ void load_b_t(uint32_t baseH, uint32_t baseL, int kk, int lane,
                                         uint32_t bh[8][2], uint32_t bl[8][2]) {
#pragma unroll
    for (int nq = 0; nq < 4; nq++) {
        uint32_t r[4], s[4];
        ldsm_x4_t(baseH, kk, nq * 16, lane, r);
        ldsm_x4_t(baseL, kk, nq * 16, lane, s);
        bh[2*nq][0] = r[0]; bh[2*nq][1] = r[1]; bh[2*nq+1][0] = r[2]; bh[2*nq+1][1] = r[3];
        bl[2*nq][0] = s[0]; bl[2*nq][1] = s[1]; bl[2*nq+1][0] = s[2]; bl[2*nq+1][1] = s[3];
    }
}

// ===========================================================================
// Preprocess: qkv fp32 -> split bf16 hi/lo arrays, q scaled by 2
// ===========================================================================
__global__ __launch_bounds__(256) void prep(const float* __restrict__ qkv) {
    int idx = blockIdx.x * 256 + threadIdx.x;      // one thread per 2 elems, src order
    int c2 = idx & 31;
    int h  = (idx >> 5) & 15;
    int w  = (idx >> 9) % 3;
    int sb = idx / 1536;
    int s  = sb & (S_ - 1);
    int b  = sb >> 11;
    float2 v = *reinterpret_cast<const float2*>(qkv + (size_t)idx * 2);
    float scale = (w == 0) ? 2.0f : 1.0f;
    uint32_t hp, lp;
    split_pair(v.x * scale, v.y * scale, hp, lp);
    size_t dst = ((size_t)(b * 16 + h) * S_ + s) * 32 + c2;
    if (w == 0)      { g_q2h[dst] = hp; g_q2l[dst] = lp; }
    else if (w == 1) { g_kh[dst]  = hp; g_kl[dst]  = lp; }
    else             { g_vh[dst]  = hp; g_vl[dst]  = lp; }
}

// smem offsets
#define SMQ_HI 0
#define SMQ_LO 16384
#define SMK(st) (32768 + (st) * 16384)        // hi; lo at +8192
#define SMV(st) (65536 + (st) * 16384)        // pass B only
#define SMEM_A_BYTES 65536
#define SMEM_B_BYTES 98304

// ===========================================================================
// Pass A: o2 = (tril(2q kT)) k / 2, stored negated: g_o2 = -o2
// ===========================================================================
__global__ __launch_bounds__(256) void passA() {
    int bh = blockIdx.y, tt = 15 - (int)blockIdx.x;
    extern __shared__ __align__(1024) char smem[];
    uint32_t sb = smem_u32(smem);
    int tid = threadIdx.x, lane = tid & 31, wid = tid >> 5;
    int warp_m = wid * 16;
    int nch = 2 * tt + 2;

    const uint32_t* qH = g_q2h + ((size_t)bh * S_ + tt * 128) * 32;
    const uint32_t* qL = g_q2l + ((size_t)bh * S_ + tt * 128) * 32;
    stage_panel(qH, qL, smem + SMQ_HI, smem + SMQ_LO, 128, tid);

    const uint32_t* kH0 = g_kh + (size_t)bh * S_ * 32;
    const uint32_t* kL0 = g_kl + (size_t)bh * S_ * 32;
    issue_panel(kH0, kL0, sb + SMK(0), sb + SMK(0) + 8192, tid);
    CP_COMMIT();
    __syncthreads();

    uint32_t qh[4][4], ql[4][4];
#pragma unroll
    for (int kf = 0; kf < 4; kf++) {
        ldsm_x4(sb + SMQ_HI, warp_m, kf * 16, lane, qh[kf]);
        ldsm_x4(sb + SMQ_LO, warp_m, kf * 16, lane, ql[kf]);
    }

    float o2acc[8][4] = {};
    int t0 = tt * 128 + warp_m + (lane >> 2);
    int cp0 = (lane & 3) * 2;

    for (int ch = 0; ch < nch; ch++) {
        if (ch + 1 < nch) {
            issue_panel(kH0 + (size_t)(ch + 1) * 64 * 32, kL0 + (size_t)(ch + 1) * 64 * 32,
                        sb + SMK((ch + 1) & 1), sb + SMK((ch + 1) & 1) + 8192, tid);
            CP_COMMIT();
            CP_WAIT1();
        } else {
            CP_WAIT0();
        }
        __syncthreads();

        uint32_t kb = sb + SMK(ch & 1), kbl = kb + 8192;
        // s1' = 2 q kT  (n = s)
        float s1[8][4] = {};
#pragma unroll
        for (int kd = 0; kd < 4; kd++) {
            uint32_t bh_[8][2], bl_[8][2];
            load_b_nt(kb, kbl, kd * 16, lane, bh_, bl_);
#pragma unroll
            for (int nf = 0; nf < 8; nf++) {
                mma16816(s1[nf], qh[kd], bh_[nf]);
                mma16816(s1[nf], qh[kd], bl_[nf]);
                mma16816(s1[nf], ql[kd], bh_[nf]);
            }
        }
        // causal mask
#pragma unroll
        for (int nf = 0; nf < 8; nf++)
#pragma unroll
            for (int e = 0; e < 4; e++) {
                int srow = t0 + ((e >> 1) << 3);
                int scol = ch * 64 + nf * 8 + cp0 + (e & 1);
                if (scol > srow) s1[nf][e] = 0.0f;
            }
        uint32_t ah[4][4], al[4][4];
        acc_to_afrag(s1, ah, al);
        // o2 += s1' k  (k-dim = s, trans B)
#pragma unroll
        for (int ks = 0; ks < 4; ks++) {
            uint32_t bh_[8][2], bl_[8][2];
            load_b_t(kb, kbl, ks * 16, lane, bh_, bl_);
#pragma unroll
            for (int nf = 0; nf < 8; nf++) {
                mma16816(o2acc[nf], ah[ks], bh_[nf]);
                mma16816(o2acc[nf], ah[ks], bl_[nf]);
                mma16816(o2acc[nf], al[ks], bh_[nf]);
            }
        }
        __syncthreads();
    }

    // store -o2 = -0.5 * o2acc, split
#pragma unroll
    for (int half = 0; half < 2; half++) {
        int t = t0 + half * 8;
        uint32_t* oh = g_o2h + ((size_t)bh * S_ + t) * 32;
        uint32_t* ol = g_o2l + ((size_t)bh * S_ + t) * 32;
#pragma unroll
        for (int nf = 0; nf < 8; nf++) {
            uint32_t hp, lp;
            split_pair(-0.5f * o2acc[nf][half * 2 + 0], -0.5f * o2acc[nf][half * 2 + 1], hp, lp);
            oh[nf * 4 + (lane & 3)] = hp;
            ol[nf * 4 + (lane & 3)] = lp;
        }
    }
}

// ===========================================================================
// Pass B: out = tril(2q kT + (-o2) kT) v
// ===========================================================================
__global__ __launch_bounds__(256) void passB(float* __restrict__ out) {
    int bh = blockIdx.y, tt = 15 - (int)blockIdx.x;
    extern __shared__ __align__(1024) char smem[];
    uint32_t sb = smem_u32(smem);
    int tid = threadIdx.x, lane = tid & 31, wid = tid >> 5;
    int warp_m = wid * 16;
    int b = bh >> 4, h = bh & 15;
    int nch = 2 * tt + 2;

    const uint32_t* kH0 = g_kh + (size_t)bh * S_ * 32;
    const uint32_t* kL0 = g_kl + (size_t)bh * S_ * 32;
    const uint32_t* vH0 = g_vh + (size_t)bh * S_ * 32;
    const uint32_t* vL0 = g_vl + (size_t)bh * S_ * 32;
    issue_panel(kH0, kL0, sb + SMK(0), sb + SMK(0) + 8192, tid);
    issue_panel(vH0, vL0, sb + SMV(0), sb + SMV(0) + 8192, tid);
    CP_COMMIT();

    // stage q, extract frags
    const uint32_t* qH = g_q2h + ((size_t)bh * S_ + tt * 128) * 32;
    const uint32_t* qL = g_q2l + ((size_t)bh * S_ + tt * 128) * 32;
    stage_panel(qH, qL, smem + SMQ_HI, smem + SMQ_LO, 128, tid);
    __syncthreads();
    uint32_t qh[4][4], ql[4][4];
#pragma unroll
    for (int kf = 0; kf < 4; kf++) {
        ldsm_x4(sb + SMQ_HI, warp_m, kf * 16, lane, qh[kf]);
        ldsm_x4(sb + SMQ_LO, warp_m, kf * 16, lane, ql[kf]);
    }
    __syncthreads();
    // stage -o2 over the q region, extract frags
    const uint32_t* oH = g_o2h + ((size_t)bh * S_ + tt * 128) * 32;
    const uint32_t* oL = g_o2l + ((size_t)bh * S_ + tt * 128) * 32;
    stage_panel(oH, oL, smem + SMQ_HI, smem + SMQ_LO, 128, tid);
    __syncthreads();
    uint32_t oh[4][4], ol[4][4];
#pragma unroll
    for (int kf = 0; kf < 4; kf++) {
        ldsm_x4(sb + SMQ_HI, warp_m, kf * 16, lane, oh[kf]);
        ldsm_x4(sb + SMQ_LO, warp_m, kf * 16, lane, ol[kf]);
    }

    float outacc[8][4] = {};
    int t0 = tt * 128 + warp_m + (lane >> 2);
    int cp0 = (lane & 3) * 2;

    for (int ch = 0; ch < nch; ch++) {
        if (ch + 1 < nch) {
            int st = (ch + 1) & 1;
            issue_panel(kH0 + (size_t)(ch + 1) * 64 * 32, kL0 + (size_t)(ch + 1) * 64 * 32,
                        sb + SMK(st), sb + SMK(st) + 8192, tid);
            issue_panel(vH0 + (size_t)(ch + 1) * 64 * 32, vL0 + (size_t)(ch + 1) * 64 * 32,
                        sb + SMV(st), sb + SMV(st) + 8192, tid);
            CP_COMMIT();
            CP_WAIT1();
        } else {
            CP_WAIT0();
        }
        __syncthreads();

        uint32_t kb = sb + SMK(ch & 1), kbl = kb + 8192;
        uint32_t vb = sb + SMV(ch & 1), vbl = vb + 8192;
        // a = 2 q kT - o2 kT  (single accumulator; o2 stored negated)
        float a[8][4] = {};
#pragma unroll
        for (int kd = 0; kd < 4; kd++) {
            uint32_t bh_[8][2], bl_[8][2];
            load_b_nt(kb, kbl, kd * 16, lane, bh_, bl_);
#pragma unroll
            for (int nf = 0; nf < 8; nf++) {
                mma16816(a[nf], qh[kd], bh_[nf]);
                mma16816(a[nf], qh[kd], bl_[nf]);
                mma16816(a[nf], ql[kd], bh_[nf]);
                mma16816(a[nf], oh[kd], bh_[nf]);
                mma16816(a[nf], oh[kd], bl_[nf]);
                mma16816(a[nf], ol[kd], bh_[nf]);
            }
        }
        // causal mask
#pragma unroll
        for (int nf = 0; nf < 8; nf++)
#pragma unroll
            for (int e = 0; e < 4; e++) {
                int srow = t0 + ((e >> 1) << 3);
                int scol = ch * 64 + nf * 8 + cp0 + (e & 1);
                if (scol > srow) a[nf][e] = 0.0f;
            }
        uint32_t ah[4][4], al[4][4];
        acc_to_afrag(a, ah, al);
        // out += a v  (k-dim = s, trans B)
#pragma unroll
        for (int ks = 0; ks < 4; ks++) {
            uint32_t bh_[8][2], bl_[8][2];
            load_b_t(vb, vbl, ks * 16, lane, bh_, bl_);
#pragma unroll
            for (int nf = 0; nf < 8; nf++) {
                mma16816(outacc[nf], ah[ks], bh_[nf]);
                mma16816(outacc[nf], ah[ks], bl_[nf]);
                mma16816(outacc[nf], al[ks], bh_[nf]);
            }
        }
        __syncthreads();
    }

    // out (B,S,H,D) fp32
#pragma unroll
    for (int half = 0; half < 2; half++) {
        int t = t0 + half * 8;
        float* op = out + (((size_t)(b * S_ + t)) * 16 + h) * 64;
#pragma unroll
        for (int nf = 0; nf < 8; nf++) {
            float2 v = make_float2(outacc[nf][half * 2 + 0], outacc[nf][half * 2 + 1]);
            *reinterpret_cast<float2*>(op + nf * 8 + cp0) = v;
        }
    }
}

// ===========================================================================
extern "C" void kernel_launch(void* const* d_in, const int* in_sizes, int n_in,
                              void* d_out, int out_size) {
    const float* qkv = (const float*)d_in[0];
    float* out = (float*)d_out;

    static bool attr_done = false;
    if (!attr_done) {
        cudaFuncSetAttribute(passA, cudaFuncAttributeMaxDynamicSharedMemorySize, SMEM_A_BYTES);
        cudaFuncSetAttribute(passB, cudaFuncAttributeMaxDynamicSharedMemorySize, SMEM_B_BYTES);
        attr_done = true;
    }

    prep<<<B_ * S_ * 3 * H_ * 32 / 256, 256>>>(qkv);
    dim3 grid(16, BH_);
    passA<<<grid, 256, SMEM_A_BYTES>>>();
    passB<<<grid, 256, SMEM_B_BYTES>>>(out);
}

// round 5
// speedup vs baseline: 10.7599x; 1.2274x over previous
#include <cuda_runtime.h>
#include <cuda_bf16.h>
#include <cstdint>

// Problem constants: qkv (B,S,3,H,D) fp32
#define B_   2
#define S_   2048
#define H_   16
#define D_   64
#define BH_  32

// ---------------------------------------------------------------------------
// Pre-split scratch: bf16 hi/lo, layout [bh][s][64] (rows of 128B)
// g_uh/g_ul hold u = 2q - o2 after pass A (written by passA epilogue).
// ---------------------------------------------------------------------------
__device__ uint32_t g_qh[(size_t)BH_ * S_ * 32];  // 8MB each (u32 = 2 bf16)
__device__ uint32_t g_ql[(size_t)BH_ * S_ * 32];
__device__ uint32_t g_kh[(size_t)BH_ * S_ * 32];
__device__ uint32_t g_kl[(size_t)BH_ * S_ * 32];
__device__ uint32_t g_vh[(size_t)BH_ * S_ * 32];
__device__ uint32_t g_vl[(size_t)BH_ * S_ * 32];
__device__ uint32_t g_uh[(size_t)BH_ * S_ * 32];
__device__ uint32_t g_ul[(size_t)BH_ * S_ * 32];

__device__ __forceinline__ uint32_t smem_u32(const void* p) {
    uint32_t a;
    asm("{ .reg .u64 t; cvta.to.shared.u64 t, %1; cvt.u32.u64 %0, t; }" : "=r"(a) : "l"(p));
    return a;
}
__device__ __forceinline__ uint32_t sw128(uint32_t off) { return off ^ ((off >> 3) & 0x70); }

// split pair (x0,x1) -> bf16x2 hi packed + bf16x2 lo packed
__device__ __forceinline__ void split_pair(float x0, float x1, uint32_t& hp, uint32_t& lp) {
    asm("cvt.rn.bf16x2.f32 %0, %1, %2;" : "=r"(hp) : "f"(x1), "f"(x0));
    float l0 = x0 - __uint_as_float(hp << 16);
    float l1 = x1 - __uint_as_float(hp & 0xFFFF0000u);
    asm("cvt.rn.bf16x2.f32 %0, %1, %2;" : "=r"(lp) : "f"(l1), "f"(l0));
}

// ---------------------------------------------------------------------------
// ldmatrix / mma (fragment mappings validated in rounds 3-4)
// ---------------------------------------------------------------------------
__device__ __forceinline__ void ldsm_x4(uint32_t base, int r_base, int c_base, int lane, uint32_t r[4]) {
    uint32_t off = (uint32_t)((r_base + (lane & 15)) * 128 + (c_base + ((lane >> 4) << 3)) * 2);
    uint32_t addr = base + sw128(off);
    asm volatile("ldmatrix.sync.aligned.m8n8.x4.shared.b16 {%0,%1,%2,%3}, [%4];"
                 : "=r"(r[0]), "=r"(r[1]), "=r"(r[2]), "=r"(r[3]) : "r"(addr));
}
__device__ __forceinline__ void ldsm_x4_t(uint32_t base, int r_base, int c_base, int lane, uint32_t r[4]) {
    uint32_t off = (uint32_t)((r_base + (lane & 15)) * 128 + (c_base + ((lane >> 4) << 3)) * 2);
    uint32_t addr = base + sw128(off);
    asm volatile("ldmatrix.sync.aligned.m8n8.x4.trans.shared.b16 {%0,%1,%2,%3}, [%4];"
                 : "=r"(r[0]), "=r"(r[1]), "=r"(r[2]), "=r"(r[3]) : "r"(addr));
}
__device__ __forceinline__ void mma16816(float c[4], const uint32_t a[4], const uint32_t b[2]) {
    asm volatile("mma.sync.aligned.m16n8k16.row.col.f32.bf16.bf16.f32 "
                 "{%0,%1,%2,%3}, {%4,%5,%6,%7}, {%8,%9}, {%0,%1,%2,%3};"
                 : "+f"(c[0]), "+f"(c[1]), "+f"(c[2]), "+f"(c[3])
                 : "r"(a[0]), "r"(a[1]), "r"(a[2]), "r"(a[3]), "r"(b[0]), "r"(b[1]));
}

// acc (m16 x n64, 8 frags) -> A-operand frags (m16 x k64, 4 kfrags), hi/lo split
__device__ __forceinline__ void acc_to_afrag(const float acc[8][4], uint32_t ah[4][4], uint32_t al[4][4]) {
#pragma unroll
    for (int kf = 0; kf < 4; kf++) {
        split_pair(acc[2*kf  ][0], acc[2*kf  ][1], ah[kf][0], al[kf][0]);
        split_pair(acc[2*kf  ][2], acc[2*kf  ][3], ah[kf][1], al[kf][1]);
        split_pair(acc[2*kf+1][0], acc[2*kf+1][1], ah[kf][2], al[kf][2]);
        split_pair(acc[2*kf+1][2], acc[2*kf+1][3], ah[kf][3], al[kf][3]);
    }
}

// ---------------------------------------------------------------------------
// cp.async chunk loader: 64 rows x 128B (hi + lo panels), SW128 swizzled
// ---------------------------------------------------------------------------
__device__ __forceinline__ void cpa16(uint32_t smaddr, const void* gaddr) {
    asm volatile("cp.async.cg.shared.global [%0], [%1], 16;" :: "r"(smaddr), "l"(gaddr));
}
__device__ __forceinline__ void issue_panel(const uint32_t* gH, const uint32_t* gL,
                                            uint32_t smH, uint32_t smL, int tid) {
    for (int i = tid; i < 512; i += 256) {
        int r = i >> 3, c = i & 7;
        uint32_t off = sw128((uint32_t)(r * 128 + c * 16));
        cpa16(smH + off, gH + r * 32 + c * 4);
        cpa16(smL + off, gL + r * 32 + c * 4);
    }
}
#define CP_COMMIT() asm volatile("cp.async.commit_group;" ::: "memory")
#define CP_WAIT1()  asm volatile("cp.async.wait_group 1;" ::: "memory")
#define CP_WAIT0()  asm volatile("cp.async.wait_group 0;" ::: "memory")

__device__ __forceinline__ void stage_panel(const uint32_t* gH, const uint32_t* gL,
                                            char* smH, char* smL, int rows, int tid) {
    for (int idx = tid; idx < rows * 32; idx += 256) {
        int r = idx >> 5, c = idx & 31;
        uint32_t off = sw128((uint32_t)(r * 128 + c * 4));
        *reinterpret_cast<uint32_t*>(smH + off) = gH[r * 32 + c];
        *reinterpret_cast<uint32_t*>(smL + off) = gL[r * 32 + c];
    }
}

// B-frags from k-chunk, non-trans ([n][k] panel), n=64 -> 8 frags
__device__ __forceinline__ void load_b_nt(uint32_t baseH, uint32_t baseL, int kk, int lane,
                                          uint32_t bh[8][2], uint32_t bl[8][2]) {
#pragma unroll
    for (int nq = 0; nq < 4; nq++) {
        uint32_t r[4], s[4];
        ldsm_x4(baseH, nq * 16, kk, lane, r);
        ldsm_x4(baseL, nq * 16, kk, lane, s);
        bh[2*nq][0] = r[0]; bh[2*nq][1] = r[2]; bh[2*nq+1][0] = r[1]; bh[2*nq+1][1] = r[3];
        bl[2*nq][0] = s[0]; bl[2*nq][1] = s[2]; bl[2*nq+1][0] = s[1]; bl[2*nq+1][1] = s[3];
    }
}
// B-frags trans ([k][n] panel), n=64
__device__ __forceinline__ void load_b_t(uint32_t baseH, uint32_t baseL, int kk, int lane,
                                         uint32_t bh[8][2], uint32_t bl[8][2]) {
#pragma unroll
    for (int nq = 0; nq < 4; nq++) {
        uint32_t r[4], s[4];
        ldsm_x4_t(baseH, kk, nq * 16, lane, r);
        ldsm_x4_t(baseL, kk, nq * 16, lane, s);
        bh[2*nq][0] = r[0]; bh[2*nq][1] = r[1]; bh[2*nq+1][0] = r[2]; bh[2*nq+1][1] = r[3];
        bl[2*nq][0] = s[0]; bl[2*nq][1] = s[1]; bl[2*nq+1][0] = s[2]; bl[2*nq+1][1] = s[3];
    }
}

// ===========================================================================
// Preprocess: qkv fp32 -> split bf16 hi/lo arrays (unscaled)
// ===========================================================================
__global__ __launch_bounds__(256) void prep(const float* __restrict__ qkv) {
    int idx = blockIdx.x * 256 + threadIdx.x;
    int c2 = idx & 31;
    int h  = (idx >> 5) & 15;
    int w  = (idx >> 9) % 3;
    int sb = idx / 1536;
    int s  = sb & (S_ - 1);
    int b  = sb >> 11;
    float2 v = *reinterpret_cast<const float2*>(qkv + (size_t)idx * 2);
    uint32_t hp, lp;
    split_pair(v.x, v.y, hp, lp);
    size_t dst = ((size_t)(b * 16 + h) * S_ + s) * 32 + c2;
    if (w == 0)      { g_qh[dst] = hp; g_ql[dst] = lp; }
    else if (w == 1) { g_kh[dst] = hp; g_kl[dst] = lp; }
    else             { g_vh[dst] = hp; g_vl[dst] = lp; }
}

// smem offsets
#define SMQ_HI 0
#define SMQ_LO 16384
#define SMK(st) (32768 + (st) * 16384)        // hi; lo at +8192
#define SMV(st) (65536 + (st) * 16384)        // pass B only
#define SMEM_A_BYTES 65536
#define SMEM_B_BYTES 98304

// ===========================================================================
// Pass A: o2 = tril(q kT) k ; epilogue stores u = 2q - o2 (split bf16)
// ===========================================================================
__global__ __launch_bounds__(256) void passA() {
    int bh = blockIdx.y, tt = 15 - (int)blockIdx.x;
    extern __shared__ __align__(1024) char smem[];
    uint32_t sb = smem_u32(smem);
    int tid = threadIdx.x, lane = tid & 31, wid = tid >> 5;
    int warp_m = wid * 16;
    int nch = 2 * tt + 2;

    const uint32_t* qH = g_qh + ((size_t)bh * S_ + tt * 128) * 32;
    const uint32_t* qL = g_ql + ((size_t)bh * S_ + tt * 128) * 32;
    stage_panel(qH, qL, smem + SMQ_HI, smem + SMQ_LO, 128, tid);

    const uint32_t* kH0 = g_kh + (size_t)bh * S_ * 32;
    const uint32_t* kL0 = g_kl + (size_t)bh * S_ * 32;
    issue_panel(kH0, kL0, sb + SMK(0), sb + SMK(0) + 8192, tid);
    CP_COMMIT();
    __syncthreads();

    uint32_t qh[4][4], ql[4][4];
#pragma unroll
    for (int kf = 0; kf < 4; kf++) {
        ldsm_x4(sb + SMQ_HI, warp_m, kf * 16, lane, qh[kf]);
        ldsm_x4(sb + SMQ_LO, warp_m, kf * 16, lane, ql[kf]);
    }

    float o2acc[8][4] = {};
    int t0 = tt * 128 + warp_m + (lane >> 2);
    int cp0 = (lane & 3) * 2;

    for (int ch = 0; ch < nch; ch++) {
        if (ch + 1 < nch) {
            issue_panel(kH0 + (size_t)(ch + 1) * 64 * 32, kL0 + (size_t)(ch + 1) * 64 * 32,
                        sb + SMK((ch + 1) & 1), sb + SMK((ch + 1) & 1) + 8192, tid);
            CP_COMMIT();
            CP_WAIT1();
        } else {
            CP_WAIT0();
        }
        __syncthreads();

        uint32_t kb = sb + SMK(ch & 1), kbl = kb + 8192;
        // s1 = q kT (a1 tile), n = s
        float s1[8][4] = {};
#pragma unroll
        for (int kd = 0; kd < 4; kd++) {
            uint32_t bh_[8][2], bl_[8][2];
            load_b_nt(kb, kbl, kd * 16, lane, bh_, bl_);
#pragma unroll
            for (int nf = 0; nf < 8; nf++) {
                mma16816(s1[nf], qh[kd], bh_[nf]);
                mma16816(s1[nf], qh[kd], bl_[nf]);
                mma16816(s1[nf], ql[kd], bh_[nf]);
            }
        }
        // causal mask
#pragma unroll
        for (int nf = 0; nf < 8; nf++)
#pragma unroll
            for (int e = 0; e < 4; e++) {
                int srow = t0 + ((e >> 1) << 3);
                int scol = ch * 64 + nf * 8 + cp0 + (e & 1);
                if (scol > srow) s1[nf][e] = 0.0f;
            }
        uint32_t ah[4][4], al[4][4];
        acc_to_afrag(s1, ah, al);
        // o2 += s1 k  (k-dim = s, trans B)
#pragma unroll
        for (int ks = 0; ks < 4; ks++) {
            uint32_t bh_[8][2], bl_[8][2];
            load_b_t(kb, kbl, ks * 16, lane, bh_, bl_);
#pragma unroll
            for (int nf = 0; nf < 8; nf++) {
                mma16816(o2acc[nf], ah[ks], bh_[nf]);
                mma16816(o2acc[nf], ah[ks], bl_[nf]);
                mma16816(o2acc[nf], al[ks], bh_[nf]);
            }
        }
        __syncthreads();
    }

    // u = 2q - o2 (q reconstructed from split frags at matching positions), store split
#pragma unroll
    for (int half = 0; half < 2; half++) {
        int t = t0 + half * 8;
        uint32_t* uh = g_uh + ((size_t)bh * S_ + t) * 32;
        uint32_t* ul = g_ul + ((size_t)bh * S_ + t) * 32;
#pragma unroll
        for (int nf = 0; nf < 8; nf++) {
            int reg = ((nf & 1) << 1) | half;
            uint32_t hb = qh[nf >> 1][reg], lb = ql[nf >> 1][reg];
            float q0 = __uint_as_float(hb << 16) + __uint_as_float(lb << 16);
            float q1 = __uint_as_float(hb & 0xFFFF0000u) + __uint_as_float(lb & 0xFFFF0000u);
            float u0 = 2.0f * q0 - o2acc[nf][half * 2 + 0];
            float u1 = 2.0f * q1 - o2acc[nf][half * 2 + 1];
            uint32_t hp, lp;
            split_pair(u0, u1, hp, lp);
            uh[nf * 4 + (lane & 3)] = hp;
            ul[nf * 4 + (lane & 3)] = lp;
        }
    }
}

// ===========================================================================
// Pass B: out = tril(u kT) v
// ===========================================================================
__global__ __launch_bounds__(256) void passB(float* __restrict__ out) {
    int bh = blockIdx.y, tt = 15 - (int)blockIdx.x;
    extern __shared__ __align__(1024) char smem[];
    uint32_t sb = smem_u32(smem);
    int tid = threadIdx.x, lane = tid & 31, wid = tid >> 5;
    int warp_m = wid * 16;
    int b = bh >> 4, h = bh & 15;
    int nch = 2 * tt + 2;

    const uint32_t* kH0 = g_kh + (size_t)bh * S_ * 32;
    const uint32_t* kL0 = g_kl + (size_t)bh * S_ * 32;
    const uint32_t* vH0 = g_vh + (size_t)bh * S_ * 32;
    const uint32_t* vL0 = g_vl + (size_t)bh * S_ * 32;
    issue_panel(kH0, kL0, sb + SMK(0), sb + SMK(0) + 8192, tid);
    issue_panel(vH0, vL0, sb + SMV(0), sb + SMV(0) + 8192, tid);
    CP_COMMIT();

    // stage u, extract frags
    const uint32_t* uH = g_uh + ((size_t)bh * S_ + tt * 128) * 32;
    const uint32_t* uL = g_ul + ((size_t)bh * S_ + tt * 128) * 32;
    stage_panel(uH, uL, smem + SMQ_HI, smem + SMQ_LO, 128, tid);
    __syncthreads();
    uint32_t uh[4][4], ul[4][4];
#pragma unroll
    for (int kf = 0; kf < 4; kf++) {
        ldsm_x4(sb + SMQ_HI, warp_m, kf * 16, lane, uh[kf]);
        ldsm_x4(sb + SMQ_LO, warp_m, kf * 16, lane, ul[kf]);
    }

    float outacc[8][4] = {};
    int t0 = tt * 128 + warp_m + (lane >> 2);
    int cp0 = (lane & 3) * 2;

    for (int ch = 0; ch < nch; ch++) {
        if (ch + 1 < nch) {
            int st = (ch + 1) & 1;
            issue_panel(kH0 + (size_t)(ch + 1) * 64 * 32, kL0 + (size_t)(ch + 1) * 64 * 32,
                        sb + SMK(st), sb + SMK(st) + 8192, tid);
            issue_panel(vH0 + (size_t)(ch + 1) * 64 * 32, vL0 + (size_t)(ch + 1) * 64 * 32,
                        sb + SMV(st), sb + SMV(st) + 8192, tid);
            CP_COMMIT();
            CP_WAIT1();
        } else {
            CP_WAIT0();
        }
        __syncthreads();

        uint32_t kb = sb + SMK(ch & 1), kbl = kb + 8192;
        uint32_t vb = sb + SMV(ch & 1), vbl = vb + 8192;
        // a = u kT  (single accumulator)
        float a[8][4] = {};
#pragma unroll
        for (int kd = 0; kd < 4; kd++) {
            uint32_t bh_[8][2], bl_[8][2];
            load_b_nt(kb, kbl, kd * 16, lane, bh_, bl_);
#pragma unroll
            for (int nf = 0; nf < 8; nf++) {
                mma16816(a[nf], uh[kd], bh_[nf]);
                mma16816(a[nf], uh[kd], bl_[nf]);
                mma16816(a[nf], ul[kd], bh_[nf]);
            }
        }
        // causal mask
#pragma unroll
        for (int nf = 0; nf < 8; nf++)
#pragma unroll
            for (int e = 0; e < 4; e++) {
                int srow = t0 + ((e >> 1) << 3);
                int scol = ch * 64 + nf * 8 + cp0 + (e & 1);
                if (scol > srow) a[nf][e] = 0.0f;
            }
        uint32_t ah[4][4], al[4][4];
        acc_to_afrag(a, ah, al);
        // out += a v  (k-dim = s, trans B)
#pragma unroll
        for (int ks = 0; ks < 4; ks++) {
            uint32_t bh_[8][2], bl_[8][2];
            load_b_t(vb, vbl, ks * 16, lane, bh_, bl_);
#pragma unroll
            for (int nf = 0; nf < 8; nf++) {
                mma16816(outacc[nf], ah[ks], bh_[nf]);
                mma16816(outacc[nf], ah[ks], bl_[nf]);
                mma16816(outacc[nf], al[ks], bh_[nf]);
            }
        }
        __syncthreads();
    }

    // out (B,S,H,D) fp32
#pragma unroll
    for (int half = 0; half < 2; half++) {
        int t = t0 + half * 8;
        float* op = out + (((size_t)(b * S_ + t)) * 16 + h) * 64;
#pragma unroll
        for (int nf = 0; nf < 8; nf++) {
            float2 v = make_float2(outacc[nf][half * 2 + 0], outacc[nf][half * 2 + 1]);
            *reinterpret_cast<float2*>(op + nf * 8 + cp0) = v;
        }
    }
}

// ===========================================================================
extern "C" void kernel_launch(void* const* d_in, const int* in_sizes, int n_in,
                              void* d_out, int out_size) {
    const float* qkv = (const float*)d_in[0];
    float* out = (float*)d_out;

    static bool attr_done = false;
    if (!attr_done) {
        cudaFuncSetAttribute(passA, cudaFuncAttributeMaxDynamicSharedMemorySize, SMEM_A_BYTES);
        cudaFuncSetAttribute(passB, cudaFuncAttributeMaxDynamicSharedMemorySize, SMEM_B_BYTES);
        attr_done = true;
    }

    prep<<<B_ * S_ * 3 * H_ * 32 / 256, 256>>>(qkv);
    dim3 grid(16, BH_);
    passA<<<grid, 256, SMEM_A_BYTES>>>();
    passB<<<grid, 256, SMEM_B_BYTES>>>(out);
}

// round 7
// speedup vs baseline: 14.0896x; 1.3095x over previous
#include <cuda_runtime.h>
#include <cuda_fp16.h>
#include <cstdint>

// Problem constants: qkv (B,S,3,H,D) fp32
#define B_   2
#define S_   2048
#define H_   16
#define D_   64
#define BH_  32

// u is stored scaled by 1/16 to keep a = u*kT inside fp16 range; final out *= 16.
#define U_SCALE   0.0625f
#define U_UNSCALE 16.0f

// ---------------------------------------------------------------------------
// Scratch: A-side operands stored as fp16 hi/lo split; B-side (k, v) single fp16.
// Layout [bh][s][64] halves = [bh][s][32] u32, rows of 128B.
// ---------------------------------------------------------------------------
__device__ uint32_t g_qh[(size_t)BH_ * S_ * 32];
__device__ uint32_t g_ql[(size_t)BH_ * S_ * 32];
__device__ uint32_t g_k [(size_t)BH_ * S_ * 32];
__device__ uint32_t g_v [(size_t)BH_ * S_ * 32];
__device__ uint32_t g_uh[(size_t)BH_ * S_ * 32];
__device__ uint32_t g_ul[(size_t)BH_ * S_ * 32];

__device__ __forceinline__ uint32_t smem_u32(const void* p) {
    uint32_t a;
    asm("{ .reg .u64 t; cvta.to.shared.u64 t, %1; cvt.u32.u64 %0, t; }" : "=r"(a) : "l"(p));
    return a;
}
__device__ __forceinline__ uint32_t sw128(uint32_t off) { return off ^ ((off >> 3) & 0x70); }

// fp16 split: x = hi + lo with hi = rtn(x), lo = rtn(x - hi); pack pairs
__device__ __forceinline__ void split_pair(float x0, float x1, uint32_t& hp, uint32_t& lp) {
    __half h0 = __float2half_rn(x0), h1 = __float2half_rn(x1);
    float r0 = x0 - __half2float(h0), r1 = x1 - __half2float(h1);
    __half l0 = __float2half_rn(r0), l1 = __float2half_rn(r1);
    hp = (uint32_t)__half_as_ushort(h0) | ((uint32_t)__half_as_ushort(h1) << 16);
    lp = (uint32_t)__half_as_ushort(l0) | ((uint32_t)__half_as_ushort(l1) << 16);
}
__device__ __forceinline__ uint32_t pack_f16(float x0, float x1) {
    uint32_t r;
    asm("cvt.rn.f16x2.f32 %0, %1, %2;" : "=r"(r) : "f"(x1), "f"(x0));
    return r;
}

// ---------------------------------------------------------------------------
// ldmatrix / mma (fragment mappings validated in rounds 3-5)
// ---------------------------------------------------------------------------
__device__ __forceinline__ void ldsm_x4(uint32_t base, int r_base, int c_base, int lane, uint32_t r[4]) {
    uint32_t off = (uint32_t)((r_base + (lane & 15)) * 128 + (c_base + ((lane >> 4) << 3)) * 2);
    uint32_t addr = base + sw128(off);
    asm volatile("ldmatrix.sync.aligned.m8n8.x4.shared.b16 {%0,%1,%2,%3}, [%4];"
                 : "=r"(r[0]), "=r"(r[1]), "=r"(r[2]), "=r"(r[3]) : "r"(addr));
}
__device__ __forceinline__ void ldsm_x4_t(uint32_t base, int r_base, int c_base, int lane, uint32_t r[4]) {
    uint32_t off = (uint32_t)((r_base + (lane & 15)) * 128 + (c_base + ((lane >> 4) << 3)) * 2);
    uint32_t addr = base + sw128(off);
    asm volatile("ldmatrix.sync.aligned.m8n8.x4.trans.shared.b16 {%0,%1,%2,%3}, [%4];"
                 : "=r"(r[0]), "=r"(r[1]), "=r"(r[2]), "=r"(r[3]) : "r"(addr));
}
__device__ __forceinline__ void mma16816(float c[4], const uint32_t a[4], const uint32_t b[2]) {
    asm volatile("mma.sync.aligned.m16n8k16.row.col.f32.f16.f16.f32 "
                 "{%0,%1,%2,%3}, {%4,%5,%6,%7}, {%8,%9}, {%0,%1,%2,%3};"
                 : "+f"(c[0]), "+f"(c[1]), "+f"(c[2]), "+f"(c[3])
                 : "r"(a[0]), "r"(a[1]), "r"(a[2]), "r"(a[3]), "r"(b[0]), "r"(b[1]));
}

// acc (m16 x n64, 8 frags) -> A-operand frags (m16 x k64, 4 kfrags), fp16 hi/lo split
__device__ __forceinline__ void acc_to_afrag(const float acc[8][4], uint32_t ah[4][4], uint32_t al[4][4]) {
#pragma unroll
    for (int kf = 0; kf < 4; kf++) {
        split_pair(acc[2*kf  ][0], acc[2*kf  ][1], ah[kf][0], al[kf][0]);
        split_pair(acc[2*kf  ][2], acc[2*kf  ][3], ah[kf][1], al[kf][1]);
        split_pair(acc[2*kf+1][0], acc[2*kf+1][1], ah[kf][2], al[kf][2]);
        split_pair(acc[2*kf+1][2], acc[2*kf+1][3], ah[kf][3], al[kf][3]);
    }
}

// ---------------------------------------------------------------------------
// cp.async: single 64-row x 128B panel, SW128 swizzled
// ---------------------------------------------------------------------------
__device__ __forceinline__ void cpa16(uint32_t smaddr, const void* gaddr) {
    asm volatile("cp.async.cg.shared.global [%0], [%1], 16;" :: "r"(smaddr), "l"(gaddr));
}
__device__ __forceinline__ void issue_panel1(const uint32_t* g, uint32_t sm, int tid) {
    for (int i = tid; i < 512; i += 256) {
        int r = i >> 3, c = i & 7;
        uint32_t off = sw128((uint32_t)(r * 128 + c * 16));
        cpa16(sm + off, g + r * 32 + c * 4);
    }
}
#define CP_COMMIT() asm volatile("cp.async.commit_group;" ::: "memory")
#define CP_WAIT1()  asm volatile("cp.async.wait_group 1;" ::: "memory")
#define CP_WAIT0()  asm volatile("cp.async.wait_group 0;" ::: "memory")

__device__ __forceinline__ void stage_panel(const uint32_t* gH, const uint32_t* gL,
                                            char* smH, char* smL, int rows, int tid) {
    for (int idx = tid; idx < rows * 32; idx += 256) {
        int r = idx >> 5, c = idx & 31;
        uint32_t off = sw128((uint32_t)(r * 128 + c * 4));
        *reinterpret_cast<uint32_t*>(smH + off) = gH[r * 32 + c];
        *reinterpret_cast<uint32_t*>(smL + off) = gL[r * 32 + c];
    }
}

// B-frags, single panel, non-trans ([n][k]), n=64 -> 8 frags
__device__ __forceinline__ void load_b_nt1(uint32_t base, int kk, int lane, uint32_t bf[8][2]) {
#pragma unroll
    for (int nq = 0; nq < 4; nq++) {
        uint32_t r[4];
        ldsm_x4(base, nq * 16, kk, lane, r);
        bf[2*nq][0] = r[0]; bf[2*nq][1] = r[2]; bf[2*nq+1][0] = r[1]; bf[2*nq+1][1] = r[3];
    }
}
// B-frags, single panel, trans ([k][n]), n=64
__device__ __forceinline__ void load_b_t1(uint32_t base, int kk, int lane, uint32_t bf[8][2]) {
#pragma unroll
    for (int nq = 0; nq < 4; nq++) {
        uint32_t r[4];
        ldsm_x4_t(base, kk, nq * 16, lane, r);
        bf[2*nq][0] = r[0]; bf[2*nq][1] = r[1]; bf[2*nq+1][0] = r[2]; bf[2*nq+1][1] = r[3];
    }
}

// ===========================================================================
// Preprocess: qkv fp32 -> q split fp16 (hi/lo), k/v single fp16
// ===========================================================================
__global__ __launch_bounds__(256) void prep(const float* __restrict__ qkv) {
    int idx = blockIdx.x * 256 + threadIdx.x;
    int c2 = idx & 31;
    int h  = (idx >> 5) & 15;
    int w  = (idx >> 9) % 3;
    int sb = idx / 1536;
    int s  = sb & (S_ - 1);
    int b  = sb >> 11;
    float2 v = *reinterpret_cast<const float2*>(qkv + (size_t)idx * 2);
    size_t dst = ((size_t)(b * 16 + h) * S_ + s) * 32 + c2;
    if (w == 0) {
        uint32_t hp, lp;
        split_pair(v.x, v.y, hp, lp);
        g_qh[dst] = hp; g_ql[dst] = lp;
    } else if (w == 1) {
        g_k[dst] = pack_f16(v.x, v.y);
    } else {
        g_v[dst] = pack_f16(v.x, v.y);
    }
}

// smem offsets
#define SMQ_HI 0
#define SMQ_LO 16384
#define SMK(st) (32768 + (st) * 8192)
#define SMV(st) (49152 + (st) * 8192)          // pass B only
#define SMEM_A_BYTES 49152
#define SMEM_B_BYTES 65536

// ===========================================================================
// Pass A: o2 = tril(q kT) k ; epilogue stores u = (2q - o2)/16 (split fp16)
// ===========================================================================
__global__ __launch_bounds__(256) void passA() {
    int bh = blockIdx.y, tt = 15 - (int)blockIdx.x;
    extern __shared__ __align__(1024) char smem[];
    uint32_t sb = smem_u32(smem);
    int tid = threadIdx.x, lane = tid & 31, wid = tid >> 5;
    int warp_m = wid * 16;
    int nch = 2 * tt + 2;

    const uint32_t* qH = g_qh + ((size_t)bh * S_ + tt * 128) * 32;
    const uint32_t* qL = g_ql + ((size_t)bh * S_ + tt * 128) * 32;
    stage_panel(qH, qL, smem + SMQ_HI, smem + SMQ_LO, 128, tid);

    const uint32_t* k0 = g_k + (size_t)bh * S_ * 32;
    issue_panel1(k0, sb + SMK(0), tid);
    CP_COMMIT();
    __syncthreads();

    uint32_t qh[4][4], ql[4][4];
#pragma unroll
    for (int kf = 0; kf < 4; kf++) {
        ldsm_x4(sb + SMQ_HI, warp_m, kf * 16, lane, qh[kf]);
        ldsm_x4(sb + SMQ_LO, warp_m, kf * 16, lane, ql[kf]);
    }

    float o2acc[8][4] = {};
    int t0 = tt * 128 + warp_m + (lane >> 2);
    int cp0 = (lane & 3) * 2;

    for (int ch = 0; ch < nch; ch++) {
        if (ch + 1 < nch) {
            issue_panel1(k0 + (size_t)(ch + 1) * 64 * 32, sb + SMK((ch + 1) & 1), tid);
            CP_COMMIT();
            CP_WAIT1();
        } else {
            CP_WAIT0();
        }
        __syncthreads();

        uint32_t kb = sb + SMK(ch & 1);
        // s1 = q kT (a1 tile), n = s  -- 2 products
        float s1[8][4] = {};
#pragma unroll
        for (int kd = 0; kd < 4; kd++) {
            uint32_t bf[8][2];
            load_b_nt1(kb, kd * 16, lane, bf);
#pragma unroll
            for (int nf = 0; nf < 8; nf++) {
                mma16816(s1[nf], qh[kd], bf[nf]);
                mma16816(s1[nf], ql[kd], bf[nf]);
            }
        }
        // causal mask
#pragma unroll
        for (int nf = 0; nf < 8; nf++)
#pragma unroll
            for (int e = 0; e < 4; e++) {
                int srow = t0 + ((e >> 1) << 3);
                int scol = ch * 64 + nf * 8 + cp0 + (e & 1);
                if (scol > srow) s1[nf][e] = 0.0f;
            }
        uint32_t ah[4][4], al[4][4];
        acc_to_afrag(s1, ah, al);
        // o2 += s1 k  (k-dim = s, trans B) -- 2 products
#pragma unroll
        for (int ks = 0; ks < 4; ks++) {
            uint32_t bf[8][2];
            load_b_t1(kb, ks * 16, lane, bf);
#pragma unroll
            for (int nf = 0; nf < 8; nf++) {
                mma16816(o2acc[nf], ah[ks], bf[nf]);
                mma16816(o2acc[nf], al[ks], bf[nf]);
            }
        }
        __syncthreads();
    }

    // u = (2q - o2) * U_SCALE (q reconstructed from split frags), store split fp16
#pragma unroll
    for (int half = 0; half < 2; half++) {
        int t = t0 + half * 8;
        uint32_t* uh = g_uh + ((size_t)bh * S_ + t) * 32;
        uint32_t* ul = g_ul + ((size_t)bh * S_ + t) * 32;
#pragma unroll
        for (int nf = 0; nf < 8; nf++) {
            int reg = ((nf & 1) << 1) | half;
            uint32_t hb = qh[nf >> 1][reg], lb = ql[nf >> 1][reg];
            float q0 = __half2float(__ushort_as_half((unsigned short)(hb & 0xFFFF)))
                     + __half2float(__ushort_as_half((unsigned short)(lb & 0xFFFF)));
            float q1 = __half2float(__ushort_as_half((unsigned short)(hb >> 16)))
                     + __half2float(__ushort_as_half((unsigned short)(lb >> 16)));
            float u0 = (2.0f * q0 - o2acc[nf][half * 2 + 0]) * U_SCALE;
            float u1 = (2.0f * q1 - o2acc[nf][half * 2 + 1]) * U_SCALE;
            uint32_t hp, lp;
            split_pair(u0, u1, hp, lp);
            uh[nf * 4 + (lane & 3)] = hp;
            ul[nf * 4 + (lane & 3)] = lp;
        }
    }
}

// ===========================================================================
// Pass B: out = tril(u kT) v * U_UNSCALE
// ===========================================================================
__global__ __launch_bounds__(256) void passB(float* __restrict__ out) {
    int bh = blockIdx.y, tt = 15 - (int)blockIdx.x;
    extern __shared__ __align__(1024) char smem[];
    uint32_t sb = smem_u32(smem);
    int tid = threadIdx.x, lane = tid & 31, wid = tid >> 5;
    int warp_m = wid * 16;
    int b = bh >> 4, h = bh & 15;
    int nch = 2 * tt + 2;

    const uint32_t* k0 = g_k + (size_t)bh * S_ * 32;
    const uint32_t* v0 = g_v + (size_t)bh * S_ * 32;
    issue_panel1(k0, sb + SMK(0), tid);
    issue_panel1(v0, sb + SMV(0), tid);
    CP_COMMIT();

    const uint32_t* uH = g_uh + ((size_t)bh * S_ + tt * 128) * 32;
    const uint32_t* uL = g_ul + ((size_t)bh * S_ + tt * 128) * 32;
    stage_panel(uH, uL, smem + SMQ_HI, smem + SMQ_LO, 128, tid);
    __syncthreads();
    uint32_t uh[4][4], ul[4][4];
#pragma unroll
    for (int kf = 0; kf < 4; kf++) {
        ldsm_x4(sb + SMQ_HI, warp_m, kf * 16, lane, uh[kf]);
        ldsm_x4(sb + SMQ_LO, warp_m, kf * 16, lane, ul[kf]);
    }

    float outacc[8][4] = {};
    int t0 = tt * 128 + warp_m + (lane >> 2);
    int cp0 = (lane & 3) * 2;

    for (int ch = 0; ch < nch; ch++) {
        if (ch + 1 < nch) {
            int st = (ch + 1) & 1;
            issue_panel1(k0 + (size_t)(ch + 1) * 64 * 32, sb + SMK(st), tid);
            issue_panel1(v0 + (size_t)(ch + 1) * 64 * 32, sb + SMV(st), tid);
            CP_COMMIT();
            CP_WAIT1();
        } else {
            CP_WAIT0();
        }
        __syncthreads();

        uint32_t kb = sb + SMK(ch & 1);
        uint32_t vb = sb + SMV(ch & 1);
        // a = u kT -- 2 products  (|a| <= ~6e3 thanks to U_SCALE)
        float a[8][4] = {};
#pragma unroll
        for (int kd = 0; kd < 4; kd++) {
            uint32_t bf[8][2];
            load_b_nt1(kb, kd * 16, lane, bf);
#pragma unroll
            for (int nf = 0; nf < 8; nf++) {
                mma16816(a[nf], uh[kd], bf[nf]);
                mma16816(a[nf], ul[kd], bf[nf]);
            }
        }
        // causal mask
#pragma unroll
        for (int nf = 0; nf < 8; nf++)
#pragma unroll
            for (int e = 0; e < 4; e++) {
                int srow = t0 + ((e >> 1) << 3);
                int scol = ch * 64 + nf * 8 + cp0 + (e & 1);
                if (scol > srow) a[nf][e] = 0.0f;
            }
        uint32_t ah[4][4], al[4][4];
        acc_to_afrag(a, ah, al);
        // out += a v  (k-dim = s, trans B) -- 2 products
#pragma unroll
        for (int ks = 0; ks < 4; ks++) {
            uint32_t bf[8][2];
            load_b_t1(vb, ks * 16, lane, bf);
#pragma unroll
            for (int nf = 0; nf < 8; nf++) {
                mma16816(outacc[nf], ah[ks], bf[nf]);
                mma16816(outacc[nf], al[ks], bf[nf]);
            }
        }
        __syncthreads();
    }

    // out (B,S,H,D) fp32, undo U_SCALE
#pragma unroll
    for (int half = 0; half < 2; half++) {
        int t = t0 + half * 8;
        float* op = out + (((size_t)(b * S_ + t)) * 16 + h) * 64;
#pragma unroll
        for (int nf = 0; nf < 8; nf++) {
            float2 v = make_float2(outacc[nf][half * 2 + 0] * U_UNSCALE,
                                   outacc[nf][half * 2 + 1] * U_UNSCALE);
            *reinterpret_cast<float2*>(op + nf * 8 + cp0) = v;
        }
    }
}

// ===========================================================================
extern "C" void kernel_launch(void* const* d_in, const int* in_sizes, int n_in,
                              void* d_out, int out_size) {
    const float* qkv = (const float*)d_in[0];
    float* out = (float*)d_out;

    static bool attr_done = false;
    if (!attr_done) {
        cudaFuncSetAttribute(passA, cudaFuncAttributeMaxDynamicSharedMemorySize, SMEM_A_BYTES);
        cudaFuncSetAttribute(passB, cudaFuncAttributeMaxDynamicSharedMemorySize, SMEM_B_BYTES);
        attr_done = true;
    }

    prep<<<B_ * S_ * 3 * H_ * 32 / 256, 256>>>(qkv);
    dim3 grid(16, BH_);
    passA<<<grid, 256, SMEM_A_BYTES>>>();
    passB<<<grid, 256, SMEM_B_BYTES>>>(out);
}

// round 8
// speedup vs baseline: 25.5592x; 1.8140x over previous
#include <cuda_runtime.h>
#include <cuda_fp16.h>
#include <cstdint>

// Problem constants: qkv (B,S,3,H,D) fp32
#define B_   2
#define S_   2048
#define H_   16
#define D_   64
#define BH_  32

// u is stored scaled by 1/16 to keep a = u*kT inside fp16 range; final out *= 16.
#define U_SCALE   0.0625f
#define U_UNSCALE 16.0f

// ---------------------------------------------------------------------------
// Scratch: all operands plain fp16, layout [bh][s][64] halves = [bh][s][32] u32.
// ---------------------------------------------------------------------------
__device__ uint32_t g_q[(size_t)BH_ * S_ * 32];
__device__ uint32_t g_k[(size_t)BH_ * S_ * 32];
__device__ uint32_t g_v[(size_t)BH_ * S_ * 32];
__device__ uint32_t g_u[(size_t)BH_ * S_ * 32];

__device__ __forceinline__ uint32_t smem_u32(const void* p) {
    uint32_t a;
    asm("{ .reg .u64 t; cvta.to.shared.u64 t, %1; cvt.u32.u64 %0, t; }" : "=r"(a) : "l"(p));
    return a;
}
__device__ __forceinline__ uint32_t sw128(uint32_t off) { return off ^ ((off >> 3) & 0x70); }

__device__ __forceinline__ uint32_t pack_f16(float x0, float x1) {
    uint32_t r;
    asm("cvt.rn.f16x2.f32 %0, %1, %2;" : "=r"(r) : "f"(x1), "f"(x0));
    return r;
}

// ---------------------------------------------------------------------------
// ldmatrix / mma (fragment mappings validated rounds 3-7)
// ---------------------------------------------------------------------------
__device__ __forceinline__ void ldsm_x4(uint32_t base, int r_base, int c_base, int lane, uint32_t r[4]) {
    uint32_t off = (uint32_t)((r_base + (lane & 15)) * 128 + (c_base + ((lane >> 4) << 3)) * 2);
    uint32_t addr = base + sw128(off);
    asm volatile("ldmatrix.sync.aligned.m8n8.x4.shared.b16 {%0,%1,%2,%3}, [%4];"
                 : "=r"(r[0]), "=r"(r[1]), "=r"(r[2]), "=r"(r[3]) : "r"(addr));
}
__device__ __forceinline__ void ldsm_x4_t(uint32_t base, int r_base, int c_base, int lane, uint32_t r[4]) {
    uint32_t off = (uint32_t)((r_base + (lane & 15)) * 128 + (c_base + ((lane >> 4) << 3)) * 2);
    uint32_t addr = base + sw128(off);
    asm volatile("ldmatrix.sync.aligned.m8n8.x4.trans.shared.b16 {%0,%1,%2,%3}, [%4];"
                 : "=r"(r[0]), "=r"(r[1]), "=r"(r[2]), "=r"(r[3]) : "r"(addr));
}
__device__ __forceinline__ void mma16816(float c[4], const uint32_t a[4], const uint32_t b[2]) {
    asm volatile("mma.sync.aligned.m16n8k16.row.col.f32.f16.f16.f32 "
                 "{%0,%1,%2,%3}, {%4,%5,%6,%7}, {%8,%9}, {%0,%1,%2,%3};"
                 : "+f"(c[0]), "+f"(c[1]), "+f"(c[2]), "+f"(c[3])
                 : "r"(a[0]), "r"(a[1]), "r"(a[2]), "r"(a[3]), "r"(b[0]), "r"(b[1]));
}

// acc (m16 x n64, 8 frags) -> A-operand frags (m16 x k64, 4 kfrags), plain fp16
__device__ __forceinline__ void acc_to_afrag(const float acc[8][4], uint32_t af[4][4]) {
#pragma unroll
    for (int kf = 0; kf < 4; kf++) {
        af[kf][0] = pack_f16(acc[2*kf  ][0], acc[2*kf  ][1]);
        af[kf][1] = pack_f16(acc[2*kf  ][2], acc[2*kf  ][3]);
        af[kf][2] = pack_f16(acc[2*kf+1][0], acc[2*kf+1][1]);
        af[kf][3] = pack_f16(acc[2*kf+1][2], acc[2*kf+1][3]);
    }
}

// ---------------------------------------------------------------------------
// cp.async: single 64-row x 128B panel, SW128 swizzled
// ---------------------------------------------------------------------------
__device__ __forceinline__ void cpa16(uint32_t smaddr, const void* gaddr) {
    asm volatile("cp.async.cg.shared.global [%0], [%1], 16;" :: "r"(smaddr), "l"(gaddr));
}
__device__ __forceinline__ void issue_panel1(const uint32_t* g, uint32_t sm, int tid) {
    for (int i = tid; i < 512; i += 256) {
        int r = i >> 3, c = i & 7;
        uint32_t off = sw128((uint32_t)(r * 128 + c * 16));
        cpa16(sm + off, g + r * 32 + c * 4);
    }
}
#define CP_COMMIT() asm volatile("cp.async.commit_group;" ::: "memory")
#define CP_WAIT1()  asm volatile("cp.async.wait_group 1;" ::: "memory")
#define CP_WAIT0()  asm volatile("cp.async.wait_group 0;" ::: "memory")

__device__ __forceinline__ void stage_panel1(const uint32_t* g, char* sm, int rows, int tid) {
    for (int idx = tid; idx < rows * 32; idx += 256) {
        int r = idx >> 5, c = idx & 31;
        uint32_t off = sw128((uint32_t)(r * 128 + c * 4));
        *reinterpret_cast<uint32_t*>(sm + off) = g[r * 32 + c];
    }
}

// B-frags, non-trans ([n][k]), n=64 -> 8 frags
__device__ __forceinline__ void load_b_nt1(uint32_t base, int kk, int lane, uint32_t bf[8][2]) {
#pragma unroll
    for (int nq = 0; nq < 4; nq++) {
        uint32_t r[4];
        ldsm_x4(base, nq * 16, kk, lane, r);
        bf[2*nq][0] = r[0]; bf[2*nq][1] = r[2]; bf[2*nq+1][0] = r[1]; bf[2*nq+1][1] = r[3];
    }
}
// B-frags, trans ([k][n]), n=64
__device__ __forceinline__ void load_b_t1(uint32_t base, int kk, int lane, uint32_t bf[8][2]) {
#pragma unroll
    for (int nq = 0; nq < 4; nq++) {
        uint32_t r[4];
        ldsm_x4_t(base, kk, nq * 16, lane, r);
        bf[2*nq][0] = r[0]; bf[2*nq][1] = r[1]; bf[2*nq+1][0] = r[2]; bf[2*nq+1][1] = r[3];
    }
}

// ===========================================================================
// Preprocess: qkv fp32 -> fp16 (q, k, v), head-major rows of 64
// ===========================================================================
__global__ __launch_bounds__(256) void prep(const float* __restrict__ qkv) {
    int idx = blockIdx.x * 256 + threadIdx.x;
    int c2 = idx & 31;
    int h  = (idx >> 5) & 15;
    int w  = (idx >> 9) % 3;
    int sb = idx / 1536;
    int s  = sb & (S_ - 1);
    int b  = sb >> 11;
    float2 v = *reinterpret_cast<const float2*>(qkv + (size_t)idx * 2);
    size_t dst = ((size_t)(b * 16 + h) * S_ + s) * 32 + c2;
    uint32_t p = pack_f16(v.x, v.y);
    if (w == 0)      g_q[dst] = p;
    else if (w == 1) g_k[dst] = p;
    else             g_v[dst] = p;
}

// smem offsets
#define SMQ 0
#define SMK(st) (16384 + (st) * 8192)
#define SMV(st) (32768 + (st) * 8192)          // pass B only
#define SMEM_A_BYTES 32768
#define SMEM_B_BYTES 49152

// ===========================================================================
// Pass A: o2 = tril(q kT) k ; epilogue stores u = (2q - o2)/16 (fp16)
// ===========================================================================
__global__ __launch_bounds__(256) void passA() {
    int bh = blockIdx.y, tt = 15 - (int)blockIdx.x;
    extern __shared__ __align__(1024) char smem[];
    uint32_t sb = smem_u32(smem);
    int tid = threadIdx.x, lane = tid & 31, wid = tid >> 5;
    int warp_m = wid * 16;
    int nch = 2 * tt + 2;

    const uint32_t* qG = g_q + ((size_t)bh * S_ + tt * 128) * 32;
    stage_panel1(qG, smem + SMQ, 128, tid);

    const uint32_t* k0 = g_k + (size_t)bh * S_ * 32;
    issue_panel1(k0, sb + SMK(0), tid);
    CP_COMMIT();
    __syncthreads();

    uint32_t qf[4][4];
#pragma unroll
    for (int kf = 0; kf < 4; kf++)
        ldsm_x4(sb + SMQ, warp_m, kf * 16, lane, qf[kf]);

    float o2acc[8][4] = {};
    int t0 = tt * 128 + warp_m + (lane >> 2);
    int cp0 = (lane & 3) * 2;

    for (int ch = 0; ch < nch; ch++) {
        if (ch + 1 < nch) {
            issue_panel1(k0 + (size_t)(ch + 1) * 64 * 32, sb + SMK((ch + 1) & 1), tid);
            CP_COMMIT();
            CP_WAIT1();
        } else {
            CP_WAIT0();
        }
        __syncthreads();

        uint32_t kb = sb + SMK(ch & 1);
        // s1 = q kT (a1 tile), n = s
        float s1[8][4] = {};
#pragma unroll
        for (int kd = 0; kd < 4; kd++) {
            uint32_t bf[8][2];
            load_b_nt1(kb, kd * 16, lane, bf);
#pragma unroll
            for (int nf = 0; nf < 8; nf++)
                mma16816(s1[nf], qf[kd], bf[nf]);
        }
        // causal mask (only chunks touching the diagonal band)
        if (ch >= 2 * tt) {
#pragma unroll
            for (int nf = 0; nf < 8; nf++)
#pragma unroll
                for (int e = 0; e < 4; e++) {
                    int srow = t0 + ((e >> 1) << 3);
                    int scol = ch * 64 + nf * 8 + cp0 + (e & 1);
                    if (scol > srow) s1[nf][e] = 0.0f;
                }
        }
        uint32_t af[4][4];
        acc_to_afrag(s1, af);
        // o2 += s1 k  (k-dim = s, trans B)
#pragma unroll
        for (int ks = 0; ks < 4; ks++) {
            uint32_t bf[8][2];
            load_b_t1(kb, ks * 16, lane, bf);
#pragma unroll
            for (int nf = 0; nf < 8; nf++)
                mma16816(o2acc[nf], af[ks], bf[nf]);
        }
        __syncthreads();
    }

    // u = (2q - o2) * U_SCALE (q from frags), store fp16
#pragma unroll
    for (int half = 0; half < 2; half++) {
        int t = t0 + half * 8;
        uint32_t* uG = g_u + ((size_t)bh * S_ + t) * 32;
#pragma unroll
        for (int nf = 0; nf < 8; nf++) {
            int reg = ((nf & 1) << 1) | half;
            uint32_t qb = qf[nf >> 1][reg];
            float q0 = __half2float(__ushort_as_half((unsigned short)(qb & 0xFFFF)));
            float q1 = __half2float(__ushort_as_half((unsigned short)(qb >> 16)));
            float u0 = (2.0f * q0 - o2acc[nf][half * 2 + 0]) * U_SCALE;
            float u1 = (2.0f * q1 - o2acc[nf][half * 2 + 1]) * U_SCALE;
            uG[nf * 4 + (lane & 3)] = pack_f16(u0, u1);
        }
    }
}

// ===========================================================================
// Pass B: out = tril(u kT) v * U_UNSCALE
// ===========================================================================
__global__ __launch_bounds__(256) void passB(float* __restrict__ out) {
    int bh = blockIdx.y, tt = 15 - (int)blockIdx.x;
    extern __shared__ __align__(1024) char smem[];
    uint32_t sb = smem_u32(smem);
    int tid = threadIdx.x, lane = tid & 31, wid = tid >> 5;
    int warp_m = wid * 16;
    int b = bh >> 4, h = bh & 15;
    int nch = 2 * tt + 2;

    const uint32_t* k0 = g_k + (size_t)bh * S_ * 32;
    const uint32_t* v0 = g_v + (size_t)bh * S_ * 32;
    issue_panel1(k0, sb + SMK(0), tid);
    issue_panel1(v0, sb + SMV(0), tid);
    CP_COMMIT();

    const uint32_t* uG = g_u + ((size_t)bh * S_ + tt * 128) * 32;
    stage_panel1(uG, smem + SMQ, 128, tid);
    __syncthreads();
    uint32_t uf[4][4];
#pragma unroll
    for (int kf = 0; kf < 4; kf++)
        ldsm_x4(sb + SMQ, warp_m, kf * 16, lane, uf[kf]);

    float outacc[8][4] = {};
    int t0 = tt * 128 + warp_m + (lane >> 2);
    int cp0 = (lane & 3) * 2;

    for (int ch = 0; ch < nch; ch++) {
        if (ch + 1 < nch) {
            int st = (ch + 1) & 1;
            issue_panel1(k0 + (size_t)(ch + 1) * 64 * 32, sb + SMK(st), tid);
            issue_panel1(v0 + (size_t)(ch + 1) * 64 * 32, sb + SMV(st), tid);
            CP_COMMIT();
            CP_WAIT1();
        } else {
            CP_WAIT0();
        }
        __syncthreads();

        uint32_t kb = sb + SMK(ch & 1);
        uint32_t vb = sb + SMV(ch & 1);
        // a = u kT  (|a| <= ~6e3 thanks to U_SCALE)
        float a[8][4] = {};
#pragma unroll
        for (int kd = 0; kd < 4; kd++) {
            uint32_t bf[8][2];
            load_b_nt1(kb, kd * 16, lane, bf);
#pragma unroll
            for (int nf = 0; nf < 8; nf++)
                mma16816(a[nf], uf[kd], bf[nf]);
        }
        // causal mask (diagonal band only)
        if (ch >= 2 * tt) {
#pragma unroll
            for (int nf = 0; nf < 8; nf++)
#pragma unroll
                for (int e = 0; e < 4; e++) {
                    int srow = t0 + ((e >> 1) << 3);
                    int scol = ch * 64 + nf * 8 + cp0 + (e & 1);
                    if (scol > srow) a[nf][e] = 0.0f;
                }
        }
        uint32_t af[4][4];
        acc_to_afrag(a, af);
        // out += a v  (k-dim = s, trans B)
#pragma unroll
        for (int ks = 0; ks < 4; ks++) {
            uint32_t bf[8][2];
            load_b_t1(vb, ks * 16, lane, bf);
#pragma unroll
            for (int nf = 0; nf < 8; nf++)
                mma16816(outacc[nf], af[ks], bf[nf]);
        }
        __syncthreads();
    }

    // out (B,S,H,D) fp32, undo U_SCALE
#pragma unroll
    for (int half = 0; half < 2; half++) {
        int t = t0 + half * 8;
        float* op = out + (((size_t)(b * S_ + t)) * 16 + h) * 64;
#pragma unroll
        for (int nf = 0; nf < 8; nf++) {
            float2 v = make_float2(outacc[nf][half * 2 + 0] * U_UNSCALE,
                                   outacc[nf][half * 2 + 1] * U_UNSCALE);
            *reinterpret_cast<float2*>(op + nf * 8 + cp0) = v;
        }
    }
}

// ===========================================================================
extern "C" void kernel_launch(void* const* d_in, const int* in_sizes, int n_in,
                              void* d_out, int out_size) {
    const float* qkv = (const float*)d_in[0];
    float* out = (float*)d_out;

    static bool attr_done = false;
    if (!attr_done) {
        cudaFuncSetAttribute(passA, cudaFuncAttributeMaxDynamicSharedMemorySize, SMEM_A_BYTES);
        cudaFuncSetAttribute(passB, cudaFuncAttributeMaxDynamicSharedMemorySize, SMEM_B_BYTES);
        attr_done = true;
    }

    prep<<<B_ * S_ * 3 * H_ * 32 / 256, 256>>>(qkv);
    dim3 grid(16, BH_);
    passA<<<grid, 256, SMEM_A_BYTES>>>();
    passB<<<grid, 256, SMEM_B_BYTES>>>(out);
}

// round 9
// speedup vs baseline: 26.4234x; 1.0338x over previous
#include <cuda_runtime.h>
#include <cuda_fp16.h>
#include <cstdint>

// Problem constants: qkv (B,S,3,H,D) fp32
#define B_   2
#define S_   2048
#define H_   16
#define D_   64
#define BH_  32

// u is stored scaled by 1/16 to keep a = u*kT inside fp16 range; final out *= 16.
#define U_SCALE   0.0625f
#define U_UNSCALE 16.0f

// ---------------------------------------------------------------------------
// Scratch: q/k/v as plain fp16, layout [bh][s][64] halves = [bh][s][32] u32.
// ---------------------------------------------------------------------------
__device__ uint32_t g_q[(size_t)BH_ * S_ * 32];
__device__ uint32_t g_k[(size_t)BH_ * S_ * 32];
__device__ uint32_t g_v[(size_t)BH_ * S_ * 32];

__device__ __forceinline__ uint32_t smem_u32(const void* p) {
    uint32_t a;
    asm("{ .reg .u64 t; cvta.to.shared.u64 t, %1; cvt.u32.u64 %0, t; }" : "=r"(a) : "l"(p));
    return a;
}
__device__ __forceinline__ uint32_t sw128(uint32_t off) { return off ^ ((off >> 3) & 0x70); }

__device__ __forceinline__ uint32_t pack_f16(float x0, float x1) {
    uint32_t r;
    asm("cvt.rn.f16x2.f32 %0, %1, %2;" : "=r"(r) : "f"(x1), "f"(x0));
    return r;
}

// ---------------------------------------------------------------------------
// ldmatrix / mma (fragment mappings validated rounds 3-8)
// ---------------------------------------------------------------------------
__device__ __forceinline__ void ldsm_x4(uint32_t base, int r_base, int c_base, int lane, uint32_t r[4]) {
    uint32_t off = (uint32_t)((r_base + (lane & 15)) * 128 + (c_base + ((lane >> 4) << 3)) * 2);
    uint32_t addr = base + sw128(off);
    asm volatile("ldmatrix.sync.aligned.m8n8.x4.shared.b16 {%0,%1,%2,%3}, [%4];"
                 : "=r"(r[0]), "=r"(r[1]), "=r"(r[2]), "=r"(r[3]) : "r"(addr));
}
__device__ __forceinline__ void ldsm_x4_t(uint32_t base, int r_base, int c_base, int lane, uint32_t r[4]) {
    uint32_t off = (uint32_t)((r_base + (lane & 15)) * 128 + (c_base + ((lane >> 4) << 3)) * 2);
    uint32_t addr = base + sw128(off);
    asm volatile("ldmatrix.sync.aligned.m8n8.x4.trans.shared.b16 {%0,%1,%2,%3}, [%4];"
                 : "=r"(r[0]), "=r"(r[1]), "=r"(r[2]), "=r"(r[3]) : "r"(addr));
}
__device__ __forceinline__ void mma16816(float c[4], const uint32_t a[4], const uint32_t b[2]) {
    asm volatile("mma.sync.aligned.m16n8k16.row.col.f32.f16.f16.f32 "
                 "{%0,%1,%2,%3}, {%4,%5,%6,%7}, {%8,%9}, {%0,%1,%2,%3};"
                 : "+f"(c[0]), "+f"(c[1]), "+f"(c[2]), "+f"(c[3])
                 : "r"(a[0]), "r"(a[1]), "r"(a[2]), "r"(a[3]), "r"(b[0]), "r"(b[1]));
}

// acc (m16 x n64, 8 frags) -> A-operand frags (m16 x k64, 4 kfrags), plain fp16
__device__ __forceinline__ void acc_to_afrag(const float acc[8][4], uint32_t af[4][4]) {
#pragma unroll
    for (int kf = 0; kf < 4; kf++) {
        af[kf][0] = pack_f16(acc[2*kf  ][0], acc[2*kf  ][1]);
        af[kf][1] = pack_f16(acc[2*kf  ][2], acc[2*kf  ][3]);
        af[kf][2] = pack_f16(acc[2*kf+1][0], acc[2*kf+1][1]);
        af[kf][3] = pack_f16(acc[2*kf+1][2], acc[2*kf+1][3]);
    }
}

// ---------------------------------------------------------------------------
// cp.async: single 64-row x 128B panel, SW128 swizzled
// ---------------------------------------------------------------------------
__device__ __forceinline__ void cpa16(uint32_t smaddr, const void* gaddr) {
    asm volatile("cp.async.cg.shared.global [%0], [%1], 16;" :: "r"(smaddr), "l"(gaddr));
}
__device__ __forceinline__ void issue_panel1(const uint32_t* g, uint32_t sm, int tid) {
    for (int i = tid; i < 512; i += 256) {
        int r = i >> 3, c = i & 7;
        uint32_t off = sw128((uint32_t)(r * 128 + c * 16));
        cpa16(sm + off, g + r * 32 + c * 4);
    }
}
#define CP_COMMIT() asm volatile("cp.async.commit_group;" ::: "memory")
#define CP_WAIT1()  asm volatile("cp.async.wait_group 1;" ::: "memory")
#define CP_WAIT0()  asm volatile("cp.async.wait_group 0;" ::: "memory")

__device__ __forceinline__ void stage_panel1(const uint32_t* g, char* sm, int rows, int tid) {
    for (int idx = tid; idx < rows * 32; idx += 256) {
        int r = idx >> 5, c = idx & 31;
        uint32_t off = sw128((uint32_t)(r * 128 + c * 4));
        *reinterpret_cast<uint32_t*>(sm + off) = g[r * 32 + c];
    }
}

// B-frags, non-trans ([n][k]), n=64 -> 8 frags
__device__ __forceinline__ void load_b_nt1(uint32_t base, int kk, int lane, uint32_t bf[8][2]) {
#pragma unroll
    for (int nq = 0; nq < 4; nq++) {
        uint32_t r[4];
        ldsm_x4(base, nq * 16, kk, lane, r);
        bf[2*nq][0] = r[0]; bf[2*nq][1] = r[2]; bf[2*nq+1][0] = r[1]; bf[2*nq+1][1] = r[3];
    }
}
// B-frags, trans ([k][n]), n=64
__device__ __forceinline__ void load_b_t1(uint32_t base, int kk, int lane, uint32_t bf[8][2]) {
#pragma unroll
    for (int nq = 0; nq < 4; nq++) {
        uint32_t r[4];
        ldsm_x4_t(base, kk, nq * 16, lane, r);
        bf[2*nq][0] = r[0]; bf[2*nq][1] = r[1]; bf[2*nq+1][0] = r[2]; bf[2*nq+1][1] = r[3];
    }
}

// ===========================================================================
// Preprocess: qkv fp32 -> fp16 (q, k, v), head-major rows of 64
// ===========================================================================
__global__ __launch_bounds__(256) void prep(const float* __restrict__ qkv) {
    int idx = blockIdx.x * 256 + threadIdx.x;
    int c2 = idx & 31;
    int h  = (idx >> 5) & 15;
    int w  = (idx >> 9) % 3;
    int sb = idx / 1536;
    int s  = sb & (S_ - 1);
    int b  = sb >> 11;
    float2 v = *reinterpret_cast<const float2*>(qkv + (size_t)idx * 2);
    size_t dst = ((size_t)(b * 16 + h) * S_ + s) * 32 + c2;
    uint32_t p = pack_f16(v.x, v.y);
    if (w == 0)      g_q[dst] = p;
    else if (w == 1) g_k[dst] = p;
    else             g_v[dst] = p;
}

// smem: q staging [0,16K) (dead after prologue; v stages alias it), k stages [16K,32K)
#define SMQ 0
#define SMV(st) ((st) * 8192)
#define SMK(st) (16384 + (st) * 8192)
#define SMEM_BYTES 32768

// ===========================================================================
// Fused: phase 1 computes o2 = tril(q kT) k, u = (2q-o2)/16 kept in REGISTERS
//        phase 2 computes out = tril(u kT) v * 16
// ===========================================================================
__global__ __launch_bounds__(256) void fused(float* __restrict__ out) {
    int bh = blockIdx.y, tt = 15 - (int)blockIdx.x;
    extern __shared__ __align__(1024) char smem[];
    uint32_t sb = smem_u32(smem);
    int tid = threadIdx.x, lane = tid & 31, wid = tid >> 5;
    int warp_m = wid * 16;
    int b = bh >> 4, h = bh & 15;
    int nch = 2 * tt + 2;

    const uint32_t* k0 = g_k + (size_t)bh * S_ * 32;
    const uint32_t* v0 = g_v + (size_t)bh * S_ * 32;

    // prologue: stage q, prefetch k chunk 0
    const uint32_t* qG = g_q + ((size_t)bh * S_ + tt * 128) * 32;
    stage_panel1(qG, smem + SMQ, 128, tid);
    issue_panel1(k0, sb + SMK(0), tid);
    CP_COMMIT();
    __syncthreads();

    uint32_t qf[4][4];
#pragma unroll
    for (int kf = 0; kf < 4; kf++)
        ldsm_x4(sb + SMQ, warp_m, kf * 16, lane, qf[kf]);

    int t0 = tt * 128 + warp_m + (lane >> 2);
    int cp0 = (lane & 3) * 2;
    // this warp's rows span [tt*128+warp_m, +16); chunk fully masked if all cols above
    int row_hi = tt * 128 + warp_m + 15;

    // ---------------- phase 1: o2 ----------------
    float o2acc[8][4] = {};
    for (int ch = 0; ch < nch; ch++) {
        if (ch + 1 < nch) {
            issue_panel1(k0 + (size_t)(ch + 1) * 64 * 32, sb + SMK((ch + 1) & 1), tid);
            CP_COMMIT();
            CP_WAIT1();
        } else {
            CP_WAIT0();
        }
        __syncthreads();

        if (ch * 64 <= row_hi) {           // skip fully-masked warps
            uint32_t kb = sb + SMK(ch & 1);
            float s1[8][4] = {};
#pragma unroll
            for (int kd = 0; kd < 4; kd++) {
                uint32_t bf[8][2];
                load_b_nt1(kb, kd * 16, lane, bf);
#pragma unroll
                for (int nf = 0; nf < 8; nf++)
                    mma16816(s1[nf], qf[kd], bf[nf]);
            }
            if (ch >= 2 * tt) {            // diagonal band: causal mask
#pragma unroll
                for (int nf = 0; nf < 8; nf++)
#pragma unroll
                    for (int e = 0; e < 4; e++) {
                        int srow = t0 + ((e >> 1) << 3);
                        int scol = ch * 64 + nf * 8 + cp0 + (e & 1);
                        if (scol > srow) s1[nf][e] = 0.0f;
                    }
            }
            uint32_t af[4][4];
            acc_to_afrag(s1, af);
#pragma unroll
            for (int ks = 0; ks < 4; ks++) {
                uint32_t bf[8][2];
                load_b_t1(kb, ks * 16, lane, bf);
#pragma unroll
                for (int nf = 0; nf < 8; nf++)
                    mma16816(o2acc[nf], af[ks], bf[nf]);
            }
        }
        __syncthreads();
    }

    // u = (2q - o2) * U_SCALE directly into A-frags (acc layout == A-frag layout)
    uint32_t uf[4][4];
    {
        float uacc[8][4];
#pragma unroll
        for (int nf = 0; nf < 8; nf++)
#pragma unroll
            for (int half = 0; half < 2; half++) {
                int reg = ((nf & 1) << 1) | half;
                uint32_t qb = qf[nf >> 1][reg];
                float q0 = __half2float(__ushort_as_half((unsigned short)(qb & 0xFFFF)));
                float q1 = __half2float(__ushort_as_half((unsigned short)(qb >> 16)));
                uacc[nf][half * 2 + 0] = (2.0f * q0 - o2acc[nf][half * 2 + 0]) * U_SCALE;
                uacc[nf][half * 2 + 1] = (2.0f * q1 - o2acc[nf][half * 2 + 1]) * U_SCALE;
            }
        acc_to_afrag(uacc, uf);
    }

    // ---------------- phase 2: out ----------------
    // prefetch k+v chunk 0 (v stages alias the dead q region)
    issue_panel1(k0, sb + SMK(0), tid);
    issue_panel1(v0, sb + SMV(0), tid);
    CP_COMMIT();

    float outacc[8][4] = {};
    for (int ch = 0; ch < nch; ch++) {
        if (ch + 1 < nch) {
            int st = (ch + 1) & 1;
            issue_panel1(k0 + (size_t)(ch + 1) * 64 * 32, sb + SMK(st), tid);
            issue_panel1(v0 + (size_t)(ch + 1) * 64 * 32, sb + SMV(st), tid);
            CP_COMMIT();
            CP_WAIT1();
        } else {
            CP_WAIT0();
        }
        __syncthreads();

        if (ch * 64 <= row_hi) {           // skip fully-masked warps
            uint32_t kb = sb + SMK(ch & 1);
            uint32_t vb = sb + SMV(ch & 1);
            float a[8][4] = {};
#pragma unroll
            for (int kd = 0; kd < 4; kd++) {
                uint32_t bf[8][2];
                load_b_nt1(kb, kd * 16, lane, bf);
#pragma unroll
                for (int nf = 0; nf < 8; nf++)
                    mma16816(a[nf], uf[kd], bf[nf]);
            }
            if (ch >= 2 * tt) {
#pragma unroll
                for (int nf = 0; nf < 8; nf++)
#pragma unroll
                    for (int e = 0; e < 4; e++) {
                        int srow = t0 + ((e >> 1) << 3);
                        int scol = ch * 64 + nf * 8 + cp0 + (e & 1);
                        if (scol > srow) a[nf][e] = 0.0f;
                    }
            }
            uint32_t af[4][4];
            acc_to_afrag(a, af);
#pragma unroll
            for (int ks = 0; ks < 4; ks++) {
                uint32_t bf[8][2];
                load_b_t1(vb, ks * 16, lane, bf);
#pragma unroll
                for (int nf = 0; nf < 8; nf++)
                    mma16816(outacc[nf], af[ks], bf[nf]);
            }
        }
        __syncthreads();
    }

    // out (B,S,H,D) fp32, undo U_SCALE
#pragma unroll
    for (int half = 0; half < 2; half++) {
        int t = t0 + half * 8;
        float* op = out + (((size_t)(b * S_ + t)) * 16 + h) * 64;
#pragma unroll
        for (int nf = 0; nf < 8; nf++) {
            float2 v = make_float2(outacc[nf][half * 2 + 0] * U_UNSCALE,
                                   outacc[nf][half * 2 + 1] * U_UNSCALE);
            *reinterpret_cast<float2*>(op + nf * 8 + cp0) = v;
        }
    }
}

// ===========================================================================
extern "C" void kernel_launch(void* const* d_in, const int* in_sizes, int n_in,
                              void* d_out, int out_size) {
    const float* qkv = (const float*)d_in[0];
    float* out = (float*)d_out;

    static bool attr_done = false;
    if (!attr_done) {
        cudaFuncSetAttribute(fused, cudaFuncAttributeMaxDynamicSharedMemorySize, SMEM_BYTES);
        attr_done = true;
    }

    prep<<<B_ * S_ * 3 * H_ * 32 / 256, 256>>>(qkv);
    dim3 grid(16, BH_);
    fused<<<grid, 256, SMEM_BYTES>>>(out);
}

// round 10
// speedup vs baseline: 26.7641x; 1.0129x over previous
#include <cuda_runtime.h>
#include <cuda_fp16.h>
#include <cstdint>

// Problem constants: qkv (B,S,3,H,D) fp32
#define B_   2
#define S_   2048
#define H_   16
#define D_   64
#define BH_  32

// u is stored scaled by 1/16 to keep a = u*kT inside fp16 range; final out *= 16.
#define U_SCALE   0.0625f
#define U_UNSCALE 16.0f

__device__ uint32_t g_q[(size_t)BH_ * S_ * 32];
__device__ uint32_t g_k[(size_t)BH_ * S_ * 32];
__device__ uint32_t g_v[(size_t)BH_ * S_ * 32];

__device__ __forceinline__ uint32_t smem_u32(const void* p) {
    uint32_t a;
    asm("{ .reg .u64 t; cvta.to.shared.u64 t, %1; cvt.u32.u64 %0, t; }" : "=r"(a) : "l"(p));
    return a;
}
__device__ __forceinline__ uint32_t sw128(uint32_t off) { return off ^ ((off >> 3) & 0x70); }

__device__ __forceinline__ uint32_t pack_f16(float x0, float x1) {
    uint32_t r;
    asm("cvt.rn.f16x2.f32 %0, %1, %2;" : "=r"(r) : "f"(x1), "f"(x0));
    return r;
}

// ---------------------------------------------------------------------------
// ldmatrix / mma (fragment mappings validated rounds 3-9)
// ---------------------------------------------------------------------------
__device__ __forceinline__ void ldsm_x4(uint32_t base, int r_base, int c_base, int lane, uint32_t r[4]) {
    uint32_t off = (uint32_t)((r_base + (lane & 15)) * 128 + (c_base + ((lane >> 4) << 3)) * 2);
    uint32_t addr = base + sw128(off);
    asm volatile("ldmatrix.sync.aligned.m8n8.x4.shared.b16 {%0,%1,%2,%3}, [%4];"
                 : "=r"(r[0]), "=r"(r[1]), "=r"(r[2]), "=r"(r[3]) : "r"(addr));
}
__device__ __forceinline__ void ldsm_x4_t(uint32_t base, int r_base, int c_base, int lane, uint32_t r[4]) {
    uint32_t off = (uint32_t)((r_base + (lane & 15)) * 128 + (c_base + ((lane >> 4) << 3)) * 2);
    uint32_t addr = base + sw128(off);
    asm volatile("ldmatrix.sync.aligned.m8n8.x4.trans.shared.b16 {%0,%1,%2,%3}, [%4];"
                 : "=r"(r[0]), "=r"(r[1]), "=r"(r[2]), "=r"(r[3]) : "r"(addr));
}
__device__ __forceinline__ void mma16816(float c[4], const uint32_t a[4], const uint32_t b[2]) {
    asm volatile("mma.sync.aligned.m16n8k16.row.col.f32.f16.f16.f32 "
                 "{%0,%1,%2,%3}, {%4,%5,%6,%7}, {%8,%9}, {%0,%1,%2,%3};"
                 : "+f"(c[0]), "+f"(c[1]), "+f"(c[2]), "+f"(c[3])
                 : "r"(a[0]), "r"(a[1]), "r"(a[2]), "r"(a[3]), "r"(b[0]), "r"(b[1]));
}

// acc (m16 x n64, 8 frags) -> A-operand frags (m16 x k64, 4 kfrags), plain fp16
__device__ __forceinline__ void acc_to_afrag(const float acc[8][4], uint32_t af[4][4]) {
#pragma unroll
    for (int kf = 0; kf < 4; kf++) {
        af[kf][0] = pack_f16(acc[2*kf  ][0], acc[2*kf  ][1]);
        af[kf][1] = pack_f16(acc[2*kf  ][2], acc[2*kf  ][3]);
        af[kf][2] = pack_f16(acc[2*kf+1][0], acc[2*kf+1][1]);
        af[kf][3] = pack_f16(acc[2*kf+1][2], acc[2*kf+1][3]);
    }
}

// ---------------------------------------------------------------------------
// cp.async: single 64-row x 128B panel, SW128 swizzled
// ---------------------------------------------------------------------------
__device__ __forceinline__ void cpa16(uint32_t smaddr, const void* gaddr) {
    asm volatile("cp.async.cg.shared.global [%0], [%1], 16;" :: "r"(smaddr), "l"(gaddr));
}
__device__ __forceinline__ void issue_panel1(const uint32_t* g, uint32_t sm, int tid) {
    for (int i = tid; i < 512; i += 256) {
        int r = i >> 3, c = i & 7;
        uint32_t off = sw128((uint32_t)(r * 128 + c * 16));
        cpa16(sm + off, g + r * 32 + c * 4);
    }
}
#define CP_COMMIT() asm volatile("cp.async.commit_group;" ::: "memory")
#define CP_WAIT1()  asm volatile("cp.async.wait_group 1;" ::: "memory")
#define CP_WAIT0()  asm volatile("cp.async.wait_group 0;" ::: "memory")

__device__ __forceinline__ void stage_panel1(const uint32_t* g, char* sm, int rows, int tid) {
    for (int idx = tid; idx < rows * 32; idx += 256) {
        int r = idx >> 5, c = idx & 31;
        uint32_t off = sw128((uint32_t)(r * 128 + c * 4));
        *reinterpret_cast<uint32_t*>(sm + off) = g[r * 32 + c];
    }
}

// B-frags, non-trans ([n][k]), n=64 -> 8 frags
__device__ __forceinline__ void load_b_nt1(uint32_t base, int kk, int lane, uint32_t bf[8][2]) {
#pragma unroll
    for (int nq = 0; nq < 4; nq++) {
        uint32_t r[4];
        ldsm_x4(base, nq * 16, kk, lane, r);
        bf[2*nq][0] = r[0]; bf[2*nq][1] = r[2]; bf[2*nq+1][0] = r[1]; bf[2*nq+1][1] = r[3];
    }
}
// B-frags, trans ([k][n]), n=64
__device__ __forceinline__ void load_b_t1(uint32_t base, int kk, int lane, uint32_t bf[8][2]) {
#pragma unroll
    for (int nq = 0; nq < 4; nq++) {
        uint32_t r[4];
        ldsm_x4_t(base, kk, nq * 16, lane, r);
        bf[2*nq][0] = r[0]; bf[2*nq][1] = r[1]; bf[2*nq+1][0] = r[2]; bf[2*nq+1][1] = r[3];
    }
}

// ===========================================================================
// Preprocess: qkv fp32 -> fp16 (q, k, v), head-major rows of 64
// ===========================================================================
__global__ __launch_bounds__(256) void prep(const float* __restrict__ qkv) {
    int idx = blockIdx.x * 256 + threadIdx.x;
    int c2 = idx & 31;
    int h  = (idx >> 5) & 15;
    int w  = (idx >> 9) % 3;
    int sb = idx / 1536;
    int s  = sb & (S_ - 1);
    int b  = sb >> 11;
    float2 v = *reinterpret_cast<const float2*>(qkv + (size_t)idx * 2);
    size_t dst = ((size_t)(b * 16 + h) * S_ + s) * 32 + c2;
    uint32_t p = pack_f16(v.x, v.y);
    if (w == 0)      g_q[dst] = p;
    else if (w == 1) g_k[dst] = p;
    else             g_v[dst] = p;
}

// smem: V ring [0,24K) (q staging [0,16K) aliases V0/V1, dead before phase 2)
//       K ring [24K,48K)
#define SMQ 0
#define SMV(st) ((st) * 8192)
#define SMK(st) (24576 + (st) * 8192)
#define SMEM_BYTES 49152

// ===========================================================================
// Fused: phase 1 computes o2 = tril(q kT) k, u = (2q-o2)/16 kept in REGISTERS
//        phase 2 computes out = tril(u kT) v * 16
// 3-stage ring buffers; ONE __syncthreads per chunk; sync-free phase seam.
// ===========================================================================
__global__ __launch_bounds__(256) void fused(float* __restrict__ out) {
    int bh = blockIdx.y, tt = 15 - (int)blockIdx.x;
    extern __shared__ __align__(1024) char smem[];
    uint32_t sb = smem_u32(smem);
    int tid = threadIdx.x, lane = tid & 31, wid = tid >> 5;
    int warp_m = wid * 16;
    int b = bh >> 4, h = bh & 15;
    int nch = 2 * tt + 2;

    const uint32_t* k0 = g_k + (size_t)bh * S_ * 32;
    const uint32_t* v0 = g_v + (size_t)bh * S_ * 32;

    // prologue: stage q, prefetch k chunks 0 and 1 (nch >= 2 always)
    const uint32_t* qG = g_q + ((size_t)bh * S_ + tt * 128) * 32;
    stage_panel1(qG, smem + SMQ, 128, tid);
    issue_panel1(k0, sb + SMK(0), tid);
    CP_COMMIT();
    issue_panel1(k0 + 2048, sb + SMK(1), tid);
    CP_COMMIT();
    __syncthreads();                          // q staged (smem stores) visible

    uint32_t qf[4][4];
#pragma unroll
    for (int kf = 0; kf < 4; kf++)
        ldsm_x4(sb + SMQ, warp_m, kf * 16, lane, qf[kf]);

    int t0 = tt * 128 + warp_m + (lane >> 2);
    int cp0 = (lane & 3) * 2;
    int row_hi = tt * 128 + warp_m + 15;      // fully-masked-warp threshold

    // ---------------- phase 1: o2 ----------------
    float o2acc[8][4] = {};
    for (int ch = 0; ch < nch; ch++) {
        if (ch + 1 < nch) CP_WAIT1(); else CP_WAIT0();
        __syncthreads();                      // data(ch) visible + all warps done with ch-1
        if (ch + 2 < nch) {
            issue_panel1(k0 + (size_t)(ch + 2) * 2048, sb + SMK((ch + 2) % 3), tid);
            CP_COMMIT();
        }

        if (ch * 64 <= row_hi) {              // skip fully-masked warps
            uint32_t kb = sb + SMK(ch % 3);
            float s1[8][4] = {};
#pragma unroll
            for (int kd = 0; kd < 4; kd++) {
                uint32_t bf[8][2];
                load_b_nt1(kb, kd * 16, lane, bf);
#pragma unroll
                for (int nf = 0; nf < 8; nf++)
                    mma16816(s1[nf], qf[kd], bf[nf]);
            }
            if (ch >= 2 * tt) {               // diagonal band: causal mask
#pragma unroll
                for (int nf = 0; nf < 8; nf++)
#pragma unroll
                    for (int e = 0; e < 4; e++) {
                        int srow = t0 + ((e >> 1) << 3);
                        int scol = ch * 64 + nf * 8 + cp0 + (e & 1);
                        if (scol > srow) s1[nf][e] = 0.0f;
                    }
            }
            uint32_t af[4][4];
            acc_to_afrag(s1, af);
#pragma unroll
            for (int ks = 0; ks < 4; ks++) {
                uint32_t bf[8][2];
                load_b_t1(kb, ks * 16, lane, bf);
#pragma unroll
                for (int nf = 0; nf < 8; nf++)
                    mma16816(o2acc[nf], af[ks], bf[nf]);
            }
        }
        // no trailing sync: next iteration's sync covers the buffer-reuse hazard
    }

    // phase-2 prefetch, issued BEFORE the u-conversion to overlap its latency.
    // k ring continues at slot nch%3 (slots (nch-1)%3, (nch-2)%3 may still be read
    // by straggler warps, but nch%3 == (nch-3)%3 is provably drained).
    // v slots alias the q staging region -- q is register-resident since prologue.
    int kb0 = nch % 3;
    issue_panel1(k0, sb + SMK(kb0), tid);
    issue_panel1(v0, sb + SMV(0), tid);
    CP_COMMIT();
    issue_panel1(k0 + 2048, sb + SMK((kb0 + 1) % 3), tid);
    issue_panel1(v0 + 2048, sb + SMV(1), tid);
    CP_COMMIT();

    // u = (2q - o2) * U_SCALE directly into A-frags (acc layout == A-frag layout)
    uint32_t uf[4][4];
    {
        float uacc[8][4];
#pragma unroll
        for (int nf = 0; nf < 8; nf++)
#pragma unroll
            for (int half = 0; half < 2; half++) {
                int reg = ((nf & 1) << 1) | half;
                uint32_t qb = qf[nf >> 1][reg];
                float q0 = __half2float(__ushort_as_half((unsigned short)(qb & 0xFFFF)));
                float q1 = __half2float(__ushort_as_half((unsigned short)(qb >> 16)));
                uacc[nf][half * 2 + 0] = (2.0f * q0 - o2acc[nf][half * 2 + 0]) * U_SCALE;
                uacc[nf][half * 2 + 1] = (2.0f * q1 - o2acc[nf][half * 2 + 1]) * U_SCALE;
            }
        acc_to_afrag(uacc, uf);
    }

    // ---------------- phase 2: out ----------------
    float outacc[8][4] = {};
    for (int ch = 0; ch < nch; ch++) {
        if (ch + 1 < nch) CP_WAIT1(); else CP_WAIT0();
        __syncthreads();
        if (ch + 2 < nch) {
            issue_panel1(k0 + (size_t)(ch + 2) * 2048, sb + SMK((kb0 + ch + 2) % 3), tid);
            issue_panel1(v0 + (size_t)(ch + 2) * 2048, sb + SMV((ch + 2) % 3), tid);
            CP_COMMIT();
        }

        if (ch * 64 <= row_hi) {
            uint32_t kb = sb + SMK((kb0 + ch) % 3);
            uint32_t vb = sb + SMV(ch % 3);
            float a[8][4] = {};
#pragma unroll
            for (int kd = 0; kd < 4; kd++) {
                uint32_t bf[8][2];
                load_b_nt1(kb, kd * 16, lane, bf);
#pragma unroll
                for (int nf = 0; nf < 8; nf++)
                    mma16816(a[nf], uf[kd], bf[nf]);
            }
            if (ch >= 2 * tt) {
#pragma unroll
                for (int nf = 0; nf < 8; nf++)
#pragma unroll
                    for (int e = 0; e < 4; e++) {
                        int srow = t0 + ((e >> 1) << 3);
                        int scol = ch * 64 + nf * 8 + cp0 + (e & 1);
                        if (scol > srow) a[nf][e] = 0.0f;
                    }
            }
            uint32_t af[4][4];
            acc_to_afrag(a, af);
#pragma unroll
            for (int ks = 0; ks < 4; ks++) {
                uint32_t bf[8][2];
                load_b_t1(vb, ks * 16, lane, bf);
#pragma unroll
                for (int nf = 0; nf < 8; nf++)
                    mma16816(outacc[nf], af[ks], bf[nf]);
            }
        }
    }

    // out (B,S,H,D) fp32, undo U_SCALE
#pragma unroll
    for (int half = 0; half < 2; half++) {
        int t = t0 + half * 8;
        float* op = out + (((size_t)(b * S_ + t)) * 16 + h) * 64;
#pragma unroll
        for (int nf = 0; nf < 8; nf++) {
            float2 v = make_float2(outacc[nf][half * 2 + 0] * U_UNSCALE,
                                   outacc[nf][half * 2 + 1] * U_UNSCALE);
            *reinterpret_cast<float2*>(op + nf * 8 + cp0) = v;
        }
    }
}

// ===========================================================================
extern "C" void kernel_launch(void* const* d_in, const int* in_sizes, int n_in,
                              void* d_out, int out_size) {
    const float* qkv = (const float*)d_in[0];
    float* out = (float*)d_out;

    static bool attr_done = false;
    if (!attr_done) {
        cudaFuncSetAttribute(fused, cudaFuncAttributeMaxDynamicSharedMemorySize, SMEM_BYTES);
        attr_done = true;
    }

    prep<<<B_ * S_ * 3 * H_ * 32 / 256, 256>>>(qkv);
    dim3 grid(16, BH_);
    fused<<<grid, 256, SMEM_BYTES>>>(out);
}

// round 11
// speedup vs baseline: 27.3805x; 1.0230x over previous
#include <cuda_runtime.h>
#include <cuda_fp16.h>
#include <cstdint>

// Problem constants: qkv (B,S,3,H,D) fp32
#define B_   2
#define S_   2048
#define H_   16
#define D_   64
#define BH_  32

// u is stored scaled by 1/16 to keep a = u*kT inside fp16 range; final out *= 16.
#define U_SCALE   0.0625f
#define U_UNSCALE 16.0f

__device__ uint32_t g_q[(size_t)BH_ * S_ * 32];
__device__ uint32_t g_k[(size_t)BH_ * S_ * 32];
__device__ uint32_t g_v[(size_t)BH_ * S_ * 32];

__device__ __forceinline__ uint32_t smem_u32(const void* p) {
    uint32_t a;
    asm("{ .reg .u64 t; cvta.to.shared.u64 t, %1; cvt.u32.u64 %0, t; }" : "=r"(a) : "l"(p));
    return a;
}
__device__ __forceinline__ uint32_t sw128(uint32_t off) { return off ^ ((off >> 3) & 0x70); }

__device__ __forceinline__ uint32_t pack_f16(float x0, float x1) {
    uint32_t r;
    asm("cvt.rn.f16x2.f32 %0, %1, %2;" : "=r"(r) : "f"(x1), "f"(x0));
    return r;
}

// ---------------------------------------------------------------------------
// ldmatrix / mma (fragment mappings validated rounds 3-10)
// ---------------------------------------------------------------------------
__device__ __forceinline__ void ldsm_x4(uint32_t base, int r_base, int c_base, int lane, uint32_t r[4]) {
    uint32_t off = (uint32_t)((r_base + (lane & 15)) * 128 + (c_base + ((lane >> 4) << 3)) * 2);
    uint32_t addr = base + sw128(off);
    asm volatile("ldmatrix.sync.aligned.m8n8.x4.shared.b16 {%0,%1,%2,%3}, [%4];"
                 : "=r"(r[0]), "=r"(r[1]), "=r"(r[2]), "=r"(r[3]) : "r"(addr));
}
__device__ __forceinline__ void ldsm_x4_t(uint32_t base, int r_base, int c_base, int lane, uint32_t r[4]) {
    uint32_t off = (uint32_t)((r_base + (lane & 15)) * 128 + (c_base + ((lane >> 4) << 3)) * 2);
    uint32_t addr = base + sw128(off);
    asm volatile("ldmatrix.sync.aligned.m8n8.x4.trans.shared.b16 {%0,%1,%2,%3}, [%4];"
                 : "=r"(r[0]), "=r"(r[1]), "=r"(r[2]), "=r"(r[3]) : "r"(addr));
}
__device__ __forceinline__ void mma16816(float c[4], const uint32_t a[4], const uint32_t b[2]) {
    asm volatile("mma.sync.aligned.m16n8k16.row.col.f32.f16.f16.f32 "
                 "{%0,%1,%2,%3}, {%4,%5,%6,%7}, {%8,%9}, {%0,%1,%2,%3};"
                 : "+f"(c[0]), "+f"(c[1]), "+f"(c[2]), "+f"(c[3])
                 : "r"(a[0]), "r"(a[1]), "r"(a[2]), "r"(a[3]), "r"(b[0]), "r"(b[1]));
}

// B-frags, trans ([k][n]), n=64 (stage 2)
__device__ __forceinline__ void load_b_t1(uint32_t base, int kk, int lane, uint32_t bf[8][2]) {
#pragma unroll
    for (int nq = 0; nq < 4; nq++) {
        uint32_t r[4];
        ldsm_x4_t(base, kk, nq * 16, lane, r);
        bf[2*nq][0] = r[0]; bf[2*nq][1] = r[1]; bf[2*nq+1][0] = r[2]; bf[2*nq+1][1] = r[3];
    }
}

// mask a half (4 nf frags starting at nfbase)
__device__ __forceinline__ void mask_half(float (&s1)[8][4], int nfbase, int colbase,
                                          int t0, int cp0) {
#pragma unroll
    for (int nf = 0; nf < 4; nf++)
#pragma unroll
        for (int e = 0; e < 4; e++) {
            int srow = t0 + ((e >> 1) << 3);
            int scol = colbase + (nfbase + nf) * 8 + cp0 + (e & 1);
            if (scol > srow) s1[nfbase + nf][e] = 0.0f;
        }
}

// conv a half: s1[2kf],s1[2kf+1] -> af[kf], for kf in {kfbase, kfbase+1}
__device__ __forceinline__ void conv_half(const float (&s1)[8][4], uint32_t (&af)[4][4], int kfbase) {
#pragma unroll
    for (int kf = kfbase; kf < kfbase + 2; kf++) {
        af[kf][0] = pack_f16(s1[2*kf  ][0], s1[2*kf  ][1]);
        af[kf][1] = pack_f16(s1[2*kf  ][2], s1[2*kf  ][3]);
        af[kf][2] = pack_f16(s1[2*kf+1][0], s1[2*kf+1][1]);
        af[kf][3] = pack_f16(s1[2*kf+1][2], s1[2*kf+1][3]);
    }
}

// ---------------------------------------------------------------------------
// One 64-col chunk: acc += tril_mask(A kT) * B2   (A frags given, B1 at kb, B2 at s2b)
// Half-interleaved: conversions overlap tensor-pipe drain.
// ---------------------------------------------------------------------------
__device__ __forceinline__ void chunk_gemm(uint32_t kb, uint32_t s2b,
                                           const uint32_t (&aF)[4][4], float (&acc)[8][4],
                                           int lane, int t0, int cp0, int colbase, bool diag) {
    float s1[8][4] = {};
    // stage1 half 0: nf 0..3 (rows 0..31 of the chunk)
#pragma unroll
    for (int kd = 0; kd < 4; kd++) {
        uint32_t r0[4], r1[4];
        ldsm_x4(kb, 0,  kd * 16, lane, r0);
        ldsm_x4(kb, 16, kd * 16, lane, r1);
        uint32_t bf[4][2];
        bf[0][0] = r0[0]; bf[0][1] = r0[2]; bf[1][0] = r0[1]; bf[1][1] = r0[3];
        bf[2][0] = r1[0]; bf[2][1] = r1[2]; bf[3][0] = r1[1]; bf[3][1] = r1[3];
#pragma unroll
        for (int nf = 0; nf < 4; nf++) mma16816(s1[nf], aF[kd], bf[nf]);
    }
    // stage1 half 1: nf 4..7
#pragma unroll
    for (int kd = 0; kd < 4; kd++) {
        uint32_t r0[4], r1[4];
        ldsm_x4(kb, 32, kd * 16, lane, r0);
        ldsm_x4(kb, 48, kd * 16, lane, r1);
        uint32_t bf[4][2];
        bf[0][0] = r0[0]; bf[0][1] = r0[2]; bf[1][0] = r0[1]; bf[1][1] = r0[3];
        bf[2][0] = r1[0]; bf[2][1] = r1[2]; bf[3][0] = r1[1]; bf[3][1] = r1[3];
#pragma unroll
        for (int nf = 0; nf < 4; nf++) mma16816(s1[4 + nf], aF[kd], bf[nf]);
    }
    // conv half 0 (overlaps drain of half-1 mmas)
    uint32_t af[4][4];
    if (diag) mask_half(s1, 0, colbase, t0, cp0);
    conv_half(s1, af, 0);
    // stage2 ks 0,1 (uses af[0..1])
#pragma unroll
    for (int ks = 0; ks < 2; ks++) {
        uint32_t bf[8][2];
        load_b_t1(s2b, ks * 16, lane, bf);
#pragma unroll
        for (int nf = 0; nf < 8; nf++) mma16816(acc[nf], af[ks], bf[nf]);
    }
    // conv half 1 (overlaps drain of ks0,1 mmas)
    if (diag) mask_half(s1, 4, colbase, t0, cp0);
    conv_half(s1, af, 2);
    // stage2 ks 2,3
#pragma unroll
    for (int ks = 2; ks < 4; ks++) {
        uint32_t bf[8][2];
        load_b_t1(s2b, ks * 16, lane, bf);
#pragma unroll
        for (int nf = 0; nf < 8; nf++) mma16816(acc[nf], af[ks], bf[nf]);
    }
}

// ---------------------------------------------------------------------------
// cp.async: single 64-row x 128B panel, SW128 swizzled
// ---------------------------------------------------------------------------
__device__ __forceinline__ void cpa16(uint32_t smaddr, const void* gaddr) {
    asm volatile("cp.async.cg.shared.global [%0], [%1], 16;" :: "r"(smaddr), "l"(gaddr));
}
__device__ __forceinline__ void issue_panel1(const uint32_t* g, uint32_t sm, int tid) {
    for (int i = tid; i < 512; i += 256) {
        int r = i >> 3, c = i & 7;
        uint32_t off = sw128((uint32_t)(r * 128 + c * 16));
        cpa16(sm + off, g + r * 32 + c * 4);
    }
}
#define CP_COMMIT() asm volatile("cp.async.commit_group;" ::: "memory")
#define CP_WAIT1()  asm volatile("cp.async.wait_group 1;" ::: "memory")
#define CP_WAIT0()  asm volatile("cp.async.wait_group 0;" ::: "memory")

__device__ __forceinline__ void stage_panel1(const uint32_t* g, char* sm, int rows, int tid) {
    for (int idx = tid; idx < rows * 32; idx += 256) {
        int r = idx >> 5, c = idx & 31;
        uint32_t off = sw128((uint32_t)(r * 128 + c * 4));
        *reinterpret_cast<uint32_t*>(sm + off) = g[r * 32 + c];
    }
}

// ===========================================================================
// Preprocess: qkv fp32 -> fp16 (q, k, v), head-major rows of 64
// ===========================================================================
__global__ __launch_bounds__(256) void prep(const float* __restrict__ qkv) {
    int idx = blockIdx.x * 256 + threadIdx.x;
    int c2 = idx & 31;
    int h  = (idx >> 5) & 15;
    int w  = (idx >> 9) % 3;
    int sb = idx / 1536;
    int s  = sb & (S_ - 1);
    int b  = sb >> 11;
    float2 v = *reinterpret_cast<const float2*>(qkv + (size_t)idx * 2);
    size_t dst = ((size_t)(b * 16 + h) * S_ + s) * 32 + c2;
    uint32_t p = pack_f16(v.x, v.y);
    if (w == 0)      g_q[dst] = p;
    else if (w == 1) g_k[dst] = p;
    else             g_v[dst] = p;
}

// smem: V ring [0,24K) (q staging [0,16K) aliases V0/V1, dead before phase 2)
//       K ring [24K,48K)
#define SMQ 0
#define SMV(st) ((st) * 8192)
#define SMK(st) (24576 + (st) * 8192)
#define SMEM_BYTES 49152

// ===========================================================================
// Fused: phase 1 computes o2 = tril(q kT) k, u = (2q-o2)/16 kept in REGISTERS
//        phase 2 computes out = tril(u kT) v * 16
// ===========================================================================
__global__ __launch_bounds__(256) void fused(float* __restrict__ out) {
    int bh = blockIdx.y, tt = 15 - (int)blockIdx.x;
    extern __shared__ __align__(1024) char smem[];
    uint32_t sb = smem_u32(smem);
    int tid = threadIdx.x, lane = tid & 31, wid = tid >> 5;
    int warp_m = wid * 16;
    int b = bh >> 4, h = bh & 15;
    int nch = 2 * tt + 2;

    const uint32_t* k0 = g_k + (size_t)bh * S_ * 32;
    const uint32_t* v0 = g_v + (size_t)bh * S_ * 32;

    // prologue: stage q, prefetch k chunks 0 and 1 (nch >= 2 always)
    const uint32_t* qG = g_q + ((size_t)bh * S_ + tt * 128) * 32;
    stage_panel1(qG, smem + SMQ, 128, tid);
    issue_panel1(k0, sb + SMK(0), tid);
    CP_COMMIT();
    issue_panel1(k0 + 2048, sb + SMK(1), tid);
    CP_COMMIT();
    __syncthreads();

    uint32_t qf[4][4];
#pragma unroll
    for (int kf = 0; kf < 4; kf++)
        ldsm_x4(sb + SMQ, warp_m, kf * 16, lane, qf[kf]);

    int t0 = tt * 128 + warp_m + (lane >> 2);
    int cp0 = (lane & 3) * 2;
    int row_hi = tt * 128 + warp_m + 15;

    // ---------------- phase 1: o2 ----------------
    float o2acc[8][4] = {};
    for (int ch = 0; ch < nch; ch++) {
        if (ch + 1 < nch) CP_WAIT1(); else CP_WAIT0();
        __syncthreads();
        if (ch + 2 < nch) {
            issue_panel1(k0 + (size_t)(ch + 2) * 2048, sb + SMK((ch + 2) % 3), tid);
            CP_COMMIT();
        }
        if (ch * 64 <= row_hi) {
            uint32_t kb = sb + SMK(ch % 3);
            chunk_gemm(kb, kb, qf, o2acc, lane, t0, cp0, ch * 64, ch >= 2 * tt);
        }
    }

    // phase-2 prefetch before u-conversion (overlap DMA with math).
    int kb0 = nch % 3;
    issue_panel1(k0, sb + SMK(kb0), tid);
    issue_panel1(v0, sb + SMV(0), tid);
    CP_COMMIT();
    issue_panel1(k0 + 2048, sb + SMK((kb0 + 1) % 3), tid);
    issue_panel1(v0 + 2048, sb + SMV(1), tid);
    CP_COMMIT();

    // u = (2q - o2) * U_SCALE directly into A-frags (acc layout == A-frag layout)
    uint32_t uf[4][4];
    {
        float uacc[8][4];
#pragma unroll
        for (int nf = 0; nf < 8; nf++)
#pragma unroll
            for (int half = 0; half < 2; half++) {
                int reg = ((nf & 1) << 1) | half;
                uint32_t qb = qf[nf >> 1][reg];
                float q0 = __half2float(__ushort_as_half((unsigned short)(qb & 0xFFFF)));
                float q1 = __half2float(__ushort_as_half((unsigned short)(qb >> 16)));
                uacc[nf][half * 2 + 0] = (2.0f * q0 - o2acc[nf][half * 2 + 0]) * U_SCALE;
                uacc[nf][half * 2 + 1] = (2.0f * q1 - o2acc[nf][half * 2 + 1]) * U_SCALE;
            }
#pragma unroll
        for (int kf = 0; kf < 4; kf++) {
            uf[kf][0] = pack_f16(uacc[2*kf  ][0], uacc[2*kf  ][1]);
            uf[kf][1] = pack_f16(uacc[2*kf  ][2], uacc[2*kf  ][3]);
            uf[kf][2] = pack_f16(uacc[2*kf+1][0], uacc[2*kf+1][1]);
            uf[kf][3] = pack_f16(uacc[2*kf+1][2], uacc[2*kf+1][3]);
        }
    }

    // ---------------- phase 2: out ----------------
    float outacc[8][4] = {};
    for (int ch = 0; ch < nch; ch++) {
        if (ch + 1 < nch) CP_WAIT1(); else CP_WAIT0();
        __syncthreads();
        if (ch + 2 < nch) {
            issue_panel1(k0 + (size_t)(ch + 2) * 2048, sb + SMK((kb0 + ch + 2) % 3), tid);
            issue_panel1(v0 + (size_t)(ch + 2) * 2048, sb + SMV((ch + 2) % 3), tid);
            CP_COMMIT();
        }
        if (ch * 64 <= row_hi) {
            uint32_t kb = sb + SMK((kb0 + ch) % 3);
            uint32_t vb = sb + SMV(ch % 3);
            chunk_gemm(kb, vb, uf, outacc, lane, t0, cp0, ch * 64, ch >= 2 * tt);
        }
    }

    // out (B,S,H,D) fp32, undo U_SCALE
#pragma unroll
    for (int half = 0; half < 2; half++) {
        int t = t0 + half * 8;
        float* op = out + (((size_t)(b * S_ + t)) * 16 + h) * 64;
#pragma unroll
        for (int nf = 0; nf < 8; nf++) {
            float2 v = make_float2(outacc[nf][half * 2 + 0] * U_UNSCALE,
                                   outacc[nf][half * 2 + 1] * U_UNSCALE);
            *reinterpret_cast<float2*>(op + nf * 8 + cp0) = v;
        }
    }
}

// ===========================================================================
extern "C" void kernel_launch(void* const* d_in, const int* in_sizes, int n_in,
                              void* d_out, int out_size) {
    const float* qkv = (const float*)d_in[0];
    float* out = (float*)d_out;

    static bool attr_done = false;
    if (!attr_done) {
        cudaFuncSetAttribute(fused, cudaFuncAttributeMaxDynamicSharedMemorySize, SMEM_BYTES);
        attr_done = true;
    }

    prep<<<B_ * S_ * 3 * H_ * 32 / 256, 256>>>(qkv);
    dim3 grid(16, BH_);
    fused<<<grid, 256, SMEM_BYTES>>>(out);
}

// round 12
// speedup vs baseline: 28.5847x; 1.0440x over previous
#include <cuda_runtime.h>
#include <cuda_fp16.h>
#include <cstdint>

// Problem constants: qkv (B,S,3,H,D) fp32
#define B_   2
#define S_   2048
#define H_   16
#define D_   64
#define BH_  32

// u is stored scaled by 1/16 to keep a = u*kT inside fp16 range; final out *= 16.
#define U_SCALE   0.0625f
#define U_UNSCALE 16.0f

__device__ uint32_t g_q[(size_t)BH_ * S_ * 32];
__device__ uint32_t g_k[(size_t)BH_ * S_ * 32];
__device__ uint32_t g_v[(size_t)BH_ * S_ * 32];

__device__ __forceinline__ uint32_t smem_u32(const void* p) {
    uint32_t a;
    asm("{ .reg .u64 t; cvta.to.shared.u64 t, %1; cvt.u32.u64 %0, t; }" : "=r"(a) : "l"(p));
    return a;
}
__device__ __forceinline__ uint32_t sw128(uint32_t off) { return off ^ ((off >> 3) & 0x70); }

__device__ __forceinline__ uint32_t pack_f16(float x0, float x1) {
    uint32_t r;
    asm("cvt.rn.f16x2.f32 %0, %1, %2;" : "=r"(r) : "f"(x1), "f"(x0));
    return r;
}

// ---------------------------------------------------------------------------
// ldmatrix / mma (fragment mappings validated rounds 3-11)
// ---------------------------------------------------------------------------
__device__ __forceinline__ void ldsm_x4(uint32_t base, int r_base, int c_base, int lane, uint32_t r[4]) {
    uint32_t off = (uint32_t)((r_base + (lane & 15)) * 128 + (c_base + ((lane >> 4) << 3)) * 2);
    uint32_t addr = base + sw128(off);
    asm volatile("ldmatrix.sync.aligned.m8n8.x4.shared.b16 {%0,%1,%2,%3}, [%4];"
                 : "=r"(r[0]), "=r"(r[1]), "=r"(r[2]), "=r"(r[3]) : "r"(addr));
}
__device__ __forceinline__ void ldsm_x4_t(uint32_t base, int r_base, int c_base, int lane, uint32_t r[4]) {
    uint32_t off = (uint32_t)((r_base + (lane & 15)) * 128 + (c_base + ((lane >> 4) << 3)) * 2);
    uint32_t addr = base + sw128(off);
    asm volatile("ldmatrix.sync.aligned.m8n8.x4.trans.shared.b16 {%0,%1,%2,%3}, [%4];"
                 : "=r"(r[0]), "=r"(r[1]), "=r"(r[2]), "=r"(r[3]) : "r"(addr));
}
__device__ __forceinline__ void mma16816(float c[4], const uint32_t a[4], const uint32_t b[2]) {
    asm volatile("mma.sync.aligned.m16n8k16.row.col.f32.f16.f16.f32 "
                 "{%0,%1,%2,%3}, {%4,%5,%6,%7}, {%8,%9}, {%0,%1,%2,%3};"
                 : "+f"(c[0]), "+f"(c[1]), "+f"(c[2]), "+f"(c[3])
                 : "r"(a[0]), "r"(a[1]), "r"(a[2]), "r"(a[3]), "r"(b[0]), "r"(b[1]));
}

// B-frags, trans ([k][n]), n=64 (stage 2)
__device__ __forceinline__ void load_b_t1(uint32_t base, int kk, int lane, uint32_t bf[8][2]) {
#pragma unroll
    for (int nq = 0; nq < 4; nq++) {
        uint32_t r[4];
        ldsm_x4_t(base, kk, nq * 16, lane, r);
        bf[2*nq][0] = r[0]; bf[2*nq][1] = r[1]; bf[2*nq+1][0] = r[2]; bf[2*nq+1][1] = r[3];
    }
}

// mask a half (4 nf frags starting at nfbase) of one m16 subtile
__device__ __forceinline__ void mask_half(float (&s1)[8][4], int nfbase, int colbase,
                                          int t0mi, int cp0) {
#pragma unroll
    for (int nf = 0; nf < 4; nf++)
#pragma unroll
        for (int e = 0; e < 4; e++) {
            int srow = t0mi + ((e >> 1) << 3);
            int scol = colbase + (nfbase + nf) * 8 + cp0 + (e & 1);
            if (scol > srow) s1[nfbase + nf][e] = 0.0f;
        }
}

// conv a half: s1[2kf],s1[2kf+1] -> af[kf], for kf in {kfbase, kfbase+1}
__device__ __forceinline__ void conv_half(const float (&s1)[8][4], uint32_t (&af)[4][4], int kfbase) {
#pragma unroll
    for (int kf = kfbase; kf < kfbase + 2; kf++) {
        af[kf][0] = pack_f16(s1[2*kf  ][0], s1[2*kf  ][1]);
        af[kf][1] = pack_f16(s1[2*kf  ][2], s1[2*kf  ][3]);
        af[kf][2] = pack_f16(s1[2*kf+1][0], s1[2*kf+1][1]);
        af[kf][3] = pack_f16(s1[2*kf+1][2], s1[2*kf+1][3]);
    }
}

// ---------------------------------------------------------------------------
// One 64-col chunk for an m32 warp tile (2 m16 subtiles share all B-frags):
//   acc[mi] += tril_mask(A[mi] kT) * B2
// ---------------------------------------------------------------------------
__device__ __forceinline__ void chunk_gemm(uint32_t kb, uint32_t s2b,
                                           const uint32_t (&aF)[2][4][4], float (&acc)[2][8][4],
                                           int lane, int t0, int cp0, int colbase, bool diag) {
    float s1[2][8][4] = {};
    // stage1 half 0: nf 0..3 (cols 0..31 of the chunk)
#pragma unroll
    for (int kd = 0; kd < 4; kd++) {
        uint32_t r0[4], r1[4];
        ldsm_x4(kb, 0,  kd * 16, lane, r0);
        ldsm_x4(kb, 16, kd * 16, lane, r1);
        uint32_t bf[4][2];
        bf[0][0] = r0[0]; bf[0][1] = r0[2]; bf[1][0] = r0[1]; bf[1][1] = r0[3];
        bf[2][0] = r1[0]; bf[2][1] = r1[2]; bf[3][0] = r1[1]; bf[3][1] = r1[3];
#pragma unroll
        for (int mi = 0; mi < 2; mi++)
#pragma unroll
            for (int nf = 0; nf < 4; nf++) mma16816(s1[mi][nf], aF[mi][kd], bf[nf]);
    }
    // stage1 half 1: nf 4..7
#pragma unroll
    for (int kd = 0; kd < 4; kd++) {
        uint32_t r0[4], r1[4];
        ldsm_x4(kb, 32, kd * 16, lane, r0);
        ldsm_x4(kb, 48, kd * 16, lane, r1);
        uint32_t bf[4][2];
        bf[0][0] = r0[0]; bf[0][1] = r0[2]; bf[1][0] = r0[1]; bf[1][1] = r0[3];
        bf[2][0] = r1[0]; bf[2][1] = r1[2]; bf[3][0] = r1[1]; bf[3][1] = r1[3];
#pragma unroll
        for (int mi = 0; mi < 2; mi++)
#pragma unroll
            for (int nf = 0; nf < 4; nf++) mma16816(s1[mi][4 + nf], aF[mi][kd], bf[nf]);
    }
    // conv half 0 (overlaps tensor-pipe drain)
    uint32_t af[2][4][4];
#pragma unroll
    for (int mi = 0; mi < 2; mi++) {
        if (diag) mask_half(s1[mi], 0, colbase, t0 + mi * 16, cp0);
        conv_half(s1[mi], af[mi], 0);
    }
    // stage2 ks 0,1 (B2-frags loaded once, used by both mi)
#pragma unroll
    for (int ks = 0; ks < 2; ks++) {
        uint32_t bf[8][2];
        load_b_t1(s2b, ks * 16, lane, bf);
#pragma unroll
        for (int mi = 0; mi < 2; mi++)
#pragma unroll
            for (int nf = 0; nf < 8; nf++) mma16816(acc[mi][nf], af[mi][ks], bf[nf]);
    }
    // conv half 1
#pragma unroll
    for (int mi = 0; mi < 2; mi++) {
        if (diag) mask_half(s1[mi], 4, colbase, t0 + mi * 16, cp0);
        conv_half(s1[mi], af[mi], 2);
    }
    // stage2 ks 2,3
#pragma unroll
    for (int ks = 2; ks < 4; ks++) {
        uint32_t bf[8][2];
        load_b_t1(s2b, ks * 16, lane, bf);
#pragma unroll
        for (int mi = 0; mi < 2; mi++)
#pragma unroll
            for (int nf = 0; nf < 8; nf++) mma16816(acc[mi][nf], af[mi][ks], bf[nf]);
    }
}

// ---------------------------------------------------------------------------
// cp.async: single 64-row x 128B panel, SW128 swizzled (128 threads)
// ---------------------------------------------------------------------------
__device__ __forceinline__ void cpa16(uint32_t smaddr, const void* gaddr) {
    asm volatile("cp.async.cg.shared.global [%0], [%1], 16;" :: "r"(smaddr), "l"(gaddr));
}
__device__ __forceinline__ void issue_panel1(const uint32_t* g, uint32_t sm, int tid) {
    for (int i = tid; i < 512; i += 128) {
        int r = i >> 3, c = i & 7;
        uint32_t off = sw128((uint32_t)(r * 128 + c * 16));
        cpa16(sm + off, g + r * 32 + c * 4);
    }
}
#define CP_COMMIT() asm volatile("cp.async.commit_group;" ::: "memory")
#define CP_WAIT1()  asm volatile("cp.async.wait_group 1;" ::: "memory")
#define CP_WAIT0()  asm volatile("cp.async.wait_group 0;" ::: "memory")

__device__ __forceinline__ void stage_panel1(const uint32_t* g, char* sm, int rows, int tid) {
    for (int idx = tid; idx < rows * 32; idx += 128) {
        int r = idx >> 5, c = idx & 31;
        uint32_t off = sw128((uint32_t)(r * 128 + c * 4));
        *reinterpret_cast<uint32_t*>(sm + off) = g[r * 32 + c];
    }
}

// ===========================================================================
// Preprocess: qkv fp32 -> fp16 (q, k, v), head-major rows of 64
// ===========================================================================
__global__ __launch_bounds__(256) void prep(const float* __restrict__ qkv) {
    int idx = blockIdx.x * 256 + threadIdx.x;
    int c2 = idx & 31;
    int h  = (idx >> 5) & 15;
    int w  = (idx >> 9) % 3;
    int sb = idx / 1536;
    int s  = sb & (S_ - 1);
    int b  = sb >> 11;
    float2 v = *reinterpret_cast<const float2*>(qkv + (size_t)idx * 2);
    size_t dst = ((size_t)(b * 16 + h) * S_ + s) * 32 + c2;
    uint32_t p = pack_f16(v.x, v.y);
    if (w == 0)      g_q[dst] = p;
    else if (w == 1) g_k[dst] = p;
    else             g_v[dst] = p;
}

// smem: V ring [0,24K) (q staging [0,16K) aliases V0/V1, dead before phase 2)
//       K ring [24K,48K)
#define SMQ 0
#define SMV(st) ((st) * 8192)
#define SMK(st) (24576 + (st) * 8192)
#define SMEM_BYTES 49152

// ===========================================================================
// Fused, 128 threads / 4 warps, m32 warp tiles.
// phase 1: o2 = tril(q kT) k, u = (2q-o2)/16 in REGISTERS
// phase 2: out = tril(u kT) v * 16
// ===========================================================================
__global__ __launch_bounds__(128, 2) void fused(float* __restrict__ out) {
    int bh = blockIdx.y, tt = 15 - (int)blockIdx.x;
    extern __shared__ __align__(1024) char smem[];
    uint32_t sb = smem_u32(smem);
    int tid = threadIdx.x, lane = tid & 31, wid = tid >> 5;
    int warp_m = wid * 32;
    int b = bh >> 4, h = bh & 15;
    int nch = 2 * tt + 2;

    const uint32_t* k0 = g_k + (size_t)bh * S_ * 32;
    const uint32_t* v0 = g_v + (size_t)bh * S_ * 32;

    // prologue: stage q, prefetch k chunks 0 and 1 (nch >= 2 always)
    const uint32_t* qG = g_q + ((size_t)bh * S_ + tt * 128) * 32;
    stage_panel1(qG, smem + SMQ, 128, tid);
    issue_panel1(k0, sb + SMK(0), tid);
    CP_COMMIT();
    issue_panel1(k0 + 2048, sb + SMK(1), tid);
    CP_COMMIT();
    __syncthreads();

    uint32_t qf[2][4][4];
#pragma unroll
    for (int mi = 0; mi < 2; mi++)
#pragma unroll
        for (int kf = 0; kf < 4; kf++)
            ldsm_x4(sb + SMQ, warp_m + mi * 16, kf * 16, lane, qf[mi][kf]);

    int t0 = tt * 128 + warp_m + (lane >> 2);
    int cp0 = (lane & 3) * 2;
    int row_hi = tt * 128 + warp_m + 31;

    // ---------------- phase 1: o2 ----------------
    float o2acc[2][8][4] = {};
    for (int ch = 0; ch < nch; ch++) {
        if (ch + 1 < nch) CP_WAIT1(); else CP_WAIT0();
        __syncthreads();
        if (ch + 2 < nch) {
            issue_panel1(k0 + (size_t)(ch + 2) * 2048, sb + SMK((ch + 2) % 3), tid);
            CP_COMMIT();
        }
        if (ch * 64 <= row_hi) {
            uint32_t kb = sb + SMK(ch % 3);
            chunk_gemm(kb, kb, qf, o2acc, lane, t0, cp0, ch * 64, ch >= 2 * tt);
        }
    }

    // phase-2 prefetch before u-conversion (overlap DMA with math).
    int kb0 = nch % 3;
    issue_panel1(k0, sb + SMK(kb0), tid);
    issue_panel1(v0, sb + SMV(0), tid);
    CP_COMMIT();
    issue_panel1(k0 + 2048, sb + SMK((kb0 + 1) % 3), tid);
    issue_panel1(v0 + 2048, sb + SMV(1), tid);
    CP_COMMIT();

    // u = (2q - o2) * U_SCALE directly into A-frags (acc layout == A-frag layout)
    uint32_t uf[2][4][4];
#pragma unroll
    for (int mi = 0; mi < 2; mi++) {
        float uacc[8][4];
#pragma unroll
        for (int nf = 0; nf < 8; nf++)
#pragma unroll
            for (int half = 0; half < 2; half++) {
                int reg = ((nf & 1) << 1) | half;
                uint32_t qb = qf[mi][nf >> 1][reg];
                float q0 = __half2float(__ushort_as_half((unsigned short)(qb & 0xFFFF)));
                float q1 = __half2float(__ushort_as_half((unsigned short)(qb >> 16)));
                uacc[nf][half * 2 + 0] = (2.0f * q0 - o2acc[mi][nf][half * 2 + 0]) * U_SCALE;
                uacc[nf][half * 2 + 1] = (2.0f * q1 - o2acc[mi][nf][half * 2 + 1]) * U_SCALE;
            }
#pragma unroll
        for (int kf = 0; kf < 4; kf++) {
            uf[mi][kf][0] = pack_f16(uacc[2*kf  ][0], uacc[2*kf  ][1]);
            uf[mi][kf][1] = pack_f16(uacc[2*kf  ][2], uacc[2*kf  ][3]);
            uf[mi][kf][2] = pack_f16(uacc[2*kf+1][0], uacc[2*kf+1][1]);
            uf[mi][kf][3] = pack_f16(uacc[2*kf+1][2], uacc[2*kf+1][3]);
        }
    }

    // ---------------- phase 2: out ----------------
    float outacc[2][8][4] = {};
    for (int ch = 0; ch < nch; ch++) {
        if (ch + 1 < nch) CP_WAIT1(); else CP_WAIT0();
        __syncthreads();
        if (ch + 2 < nch) {
            issue_panel1(k0 + (size_t)(ch + 2) * 2048, sb + SMK((kb0 + ch + 2) % 3), tid);
            issue_panel1(v0 + (size_t)(ch + 2) * 2048, sb + SMV((ch + 2) % 3), tid);
            CP_COMMIT();
        }
        if (ch * 64 <= row_hi) {
            uint32_t kb = sb + SMK((kb0 + ch) % 3);
            uint32_t vb = sb + SMV(ch % 3);
            chunk_gemm(kb, vb, uf, outacc, lane, t0, cp0, ch * 64, ch >= 2 * tt);
        }
    }

    // out (B,S,H,D) fp32, undo U_SCALE
#pragma unroll
    for (int mi = 0; mi < 2; mi++)
#pragma unroll
        for (int half = 0; half < 2; half++) {
            int t = t0 + mi * 16 + half * 8;
            float* op = out + (((size_t)(b * S_ + t)) * 16 + h) * 64;
#pragma unroll
            for (int nf = 0; nf < 8; nf++) {
                float2 v = make_float2(outacc[mi][nf][half * 2 + 0] * U_UNSCALE,
                                       outacc[mi][nf][half * 2 + 1] * U_UNSCALE);
                *reinterpret_cast<float2*>(op + nf * 8 + cp0) = v;
            }
        }
}

// ===========================================================================
extern "C" void kernel_launch(void* const* d_in, const int* in_sizes, int n_in,
                              void* d_out, int out_size) {
    const float* qkv = (const float*)d_in[0];
    float* out = (float*)d_out;

    static bool attr_done = false;
    if (!attr_done) {
        cudaFuncSetAttribute(fused, cudaFuncAttributeMaxDynamicSharedMemorySize, SMEM_BYTES);
        attr_done = true;
    }

    prep<<<B_ * S_ * 3 * H_ * 32 / 256, 256>>>(qkv);
    dim3 grid(16, BH_);
    fused<<<grid, 128, SMEM_BYTES>>>(out);
}